// round 13
// baseline (speedup 1.0000x reference)
#include <cuda_runtime.h>
#include <cuda_bf16.h>
#include <math.h>

#define Nn 384
#define Cc 128
#define NN (Nn*Nn)   // 147456

// ---------------- global scratch (no allocations allowed) ------------------
__device__ __nv_bfloat16 g_ah[(size_t)Cc*NN];
__device__ __nv_bfloat16 g_al[(size_t)Cc*NN];
__device__ __nv_bfloat16 g_bh[(size_t)Cc*NN];
__device__ __nv_bfloat16 g_bl[(size_t)Cc*NN];
__device__ float g_gate[(size_t)Cc*NN];
__device__ float g_s[(size_t)Cc*NN];

// Pre-split weights as smem tile image: per matrix hi plane [128 x 272B], then lo.
#define WPLANE 34816
#define WMAT   (2*WPLANE)
__device__ __align__(16) char g_wsp[6*WMAT];

// ---------------- helpers ---------------------------------------------------
__device__ __forceinline__ unsigned smem_u32(const void* p) {
    unsigned a;
    asm("{ .reg .u64 t; cvta.to.shared.u64 t, %1; cvt.u32.u64 %0, t; }" : "=r"(a) : "l"(p));
    return a;
}
__device__ __forceinline__ void ldsm4(unsigned r[4], unsigned addr) {
    asm volatile("ldmatrix.sync.aligned.m8n8.x4.shared.b16 {%0,%1,%2,%3}, [%4];"
        : "=r"(r[0]), "=r"(r[1]), "=r"(r[2]), "=r"(r[3]) : "r"(addr));
}
__device__ __forceinline__ void mma_bf16(float c[4], const unsigned a[4], unsigned b0, unsigned b1) {
    asm volatile("mma.sync.aligned.m16n8k16.row.col.f32.bf16.bf16.f32 "
        "{%0,%1,%2,%3}, {%4,%5,%6,%7}, {%8,%9}, {%0,%1,%2,%3};"
        : "+f"(c[0]), "+f"(c[1]), "+f"(c[2]), "+f"(c[3])
        : "r"(a[0]), "r"(a[1]), "r"(a[2]), "r"(a[3]), "r"(b0), "r"(b1));
}
__device__ __forceinline__ unsigned ldsm_addr(unsigned base, int lane, int r0, int c0, int S) {
    int row = r0 + (lane & 7) + ((lane >> 3) & 1) * 8;
    int col = c0 + ((lane >> 4) << 3);
    return base + (unsigned)((row * S + col) * 2);
}
__device__ __forceinline__ void cp16(unsigned dst, const void* src) {
    asm volatile("cp.async.cg.shared.global [%0], [%1], 16;" :: "r"(dst), "l"(src));
}
#define CP_COMMIT() asm volatile("cp.async.commit_group;" ::: "memory")
#define CP_WAIT0()  asm volatile("cp.async.wait_group 0;" ::: "memory")
#define CP_WAIT1()  asm volatile("cp.async.wait_group 1;" ::: "memory")

__device__ __forceinline__ float sigm(float x) { return 1.f / (1.f + __expf(-x)); }

__device__ __forceinline__ void split2(float a, float b, unsigned& hi, unsigned& lo) {
    __nv_bfloat16 ha = __float2bfloat16(a), hb = __float2bfloat16(b);
    float ra = a - __bfloat162float(ha), rb = b - __bfloat162float(hb);
    __nv_bfloat16 la = __float2bfloat16(ra), lb = __float2bfloat16(rb);
    hi = (unsigned)__bfloat16_as_ushort(ha) | ((unsigned)__bfloat16_as_ushort(hb) << 16);
    lo = (unsigned)__bfloat16_as_ushort(la) | ((unsigned)__bfloat16_as_ushort(lb) << 16);
}

#define STR 136      // bf16 row stride for 128-col tiles (272B)
#define APL 17408    // 64-row A plane (64*272)

// ===========================================================================
// Kernel 0: split 6 weight matrices into smem-image layout
// ===========================================================================
__global__ __launch_bounds__(256) void split_weights_kernel(
    const float* __restrict__ Wa1, const float* __restrict__ Wa2,
    const float* __restrict__ Wb1, const float* __restrict__ Wb2,
    const float* __restrict__ Wg,  const float* __restrict__ Wout)
{
    int f = blockIdx.x * 256 + threadIdx.x;       // 6*128*64 = 49152
    int m = f >> 13;
    int rem = f & 8191;
    int h = rem >> 6, c2 = rem & 63;
    const float* W = (m == 0) ? Wa1 : (m == 1) ? Wa2 : (m == 2) ? Wb1 :
                     (m == 3) ? Wb2 : (m == 4) ? Wg : Wout;
    float x0 = W[h * 128 + c2 * 2], x1 = W[h * 128 + c2 * 2 + 1];
    unsigned hi, lo; split2(x0, x1, hi, lo);
    char* basep = g_wsp + (size_t)m * WMAT;
    *(unsigned*)(basep + h * 272 + c2 * 4)          = hi;
    *(unsigned*)(basep + WPLANE + h * 272 + c2 * 4) = lo;
}

// ===========================================================================
// Kernel 1: LN(z) + 5 projections. 64-row tiles, 256 thr, occupancy 2.
// W loads pipelined via hi/lo pass split: pass1 = (ah+al)*Whi while Wlo loads,
// pass2 = ah*Wlo while Whi[m+1] loads. Epilogue stages in the Wlo region.
// smem: A hi/lo (34816) | Whi (34816) | Wlo+stage (36864) | params
// ===========================================================================
#define P_A    0
#define P_WHI  34816
#define P_WLO  69632
#define P_GIN  106496
#define P_BIN  107008
#define P_SMEM 107520
#define WHALF  2176          // 34816/16 cp16 ops per W plane

__global__ __launch_bounds__(256, 2) void proj_kernel(
    const float* __restrict__ z,
    const float* __restrict__ gin, const float* __restrict__ bin)
{
    extern __shared__ char sm[];
    const unsigned SB = smem_u32(sm);
    const int tid = threadIdx.x, lane = tid & 31, w = tid >> 5;
    const int g = lane >> 2, t2 = (lane & 3) * 2;
    const int wm = w >> 1, wn = w & 1;
    const int m0 = wm * 16;
    const size_t base = (size_t)blockIdx.x * 64;

    // issue Whi[0] immediately (overlaps z load + LN)
    {
#pragma unroll
        for (int q = 0; q < 9; ++q) {
            int t = tid + q * 256;
            if (t < WHALF) cp16(SB + P_WHI + t * 16, g_wsp + (size_t)t * 16);
        }
        CP_COMMIT();
    }

    if (tid < 128) {
        ((float*)(sm + P_GIN))[tid] = gin[tid];
        ((float*)(sm + P_BIN))[tid] = bin[tid];
    }

    // direct z load: row = tid>>2, cols q*32..q*32+31
    {
        const int row = tid >> 2, q = tid & 3;
        float zv[32];
        const float4* zp = (const float4*)(z + (base + row) * 128 + q * 32);
#pragma unroll
        for (int i = 0; i < 8; ++i) {
            float4 v = zp[i];
            zv[i * 4]     = v.x; zv[i * 4 + 1] = v.y;
            zv[i * 4 + 2] = v.z; zv[i * 4 + 3] = v.w;
        }
        float s = 0.f, s2 = 0.f;
#pragma unroll
        for (int i = 0; i < 32; ++i) { s += zv[i]; s2 += zv[i] * zv[i]; }
        s  += __shfl_xor_sync(0xffffffffu, s, 1);  s2 += __shfl_xor_sync(0xffffffffu, s2, 1);
        s  += __shfl_xor_sync(0xffffffffu, s, 2);  s2 += __shfl_xor_sync(0xffffffffu, s2, 2);
        float mu = s * (1.f / 128.f);
        float rs = rsqrtf(fmaf(-mu, mu, s2 * (1.f / 128.f)) + 1e-5f);
        __syncthreads();          // params visible
        const float* G  = (const float*)(sm + P_GIN);
        const float* Bv = (const float*)(sm + P_BIN);
#pragma unroll
        for (int c2 = 0; c2 < 16; ++c2) {
            int c = q * 32 + c2 * 2;
            float x0 = (zv[c2 * 2]     - mu) * rs * G[c]     + Bv[c];
            float x1 = (zv[c2 * 2 + 1] - mu) * rs * G[c + 1] + Bv[c + 1];
            unsigned hi, lo; split2(x0, x1, hi, lo);
            *(unsigned*)(sm + P_A       + (row * STR + c) * 2) = hi;
            *(unsigned*)(sm + P_A + APL + (row * STR + c) * 2) = lo;
        }
    }

    float keep[8][4];

    for (int m = 0; m < 5; ++m) {
        CP_WAIT0();
        __syncthreads();          // Whi[m] + A tiles visible

        // issue Wlo[m]
        {
            const char* srcb = g_wsp + (size_t)m * WMAT + WPLANE;
#pragma unroll
            for (int q = 0; q < 9; ++q) {
                int t = tid + q * 256;
                if (t < WHALF) cp16(SB + P_WLO + t * 16, srcb + (size_t)t * 16);
            }
            CP_COMMIT();
        }

        float acc[8][4];
#pragma unroll
        for (int i = 0; i < 8; ++i)
#pragma unroll
            for (int j = 0; j < 4; ++j) acc[i][j] = 0.f;

        // pass1: hi terms (ah*bh + al*bh) — reads Whi only
#pragma unroll
        for (int ks = 0; ks < 8; ++ks) {
            const int k0 = ks * 16;
            unsigned ah[4], al[4];
            ldsm4(ah, ldsm_addr(SB + P_A,       lane, m0, k0, STR));
            ldsm4(al, ldsm_addr(SB + P_A + APL, lane, m0, k0, STR));
#pragma unroll
            for (int nb = 0; nb < 4; ++nb) {
                const int n0 = wn * 64 + nb * 16;
                unsigned bh[4];
                ldsm4(bh, ldsm_addr(SB + P_WHI, lane, n0, k0, STR));
                mma_bf16(acc[nb * 2],     ah, bh[0], bh[2]);
                mma_bf16(acc[nb * 2],     al, bh[0], bh[2]);
                mma_bf16(acc[nb * 2 + 1], ah, bh[1], bh[3]);
                mma_bf16(acc[nb * 2 + 1], al, bh[1], bh[3]);
            }
        }
        CP_WAIT0();
        __syncthreads();          // Wlo ready; all warps done with pass1 (Whi free)

        // issue Whi[m+1]
        if (m < 4) {
            const char* srcb = g_wsp + (size_t)(m + 1) * WMAT;
#pragma unroll
            for (int q = 0; q < 9; ++q) {
                int t = tid + q * 256;
                if (t < WHALF) cp16(SB + P_WHI + t * 16, srcb + (size_t)t * 16);
            }
            CP_COMMIT();
        }

        // pass2: lo term (ah*bl) — reads Wlo only
#pragma unroll
        for (int ks = 0; ks < 8; ++ks) {
            const int k0 = ks * 16;
            unsigned ah[4];
            ldsm4(ah, ldsm_addr(SB + P_A, lane, m0, k0, STR));
#pragma unroll
            for (int nb = 0; nb < 4; ++nb) {
                const int n0 = wn * 64 + nb * 16;
                unsigned bl[4];
                ldsm4(bl, ldsm_addr(SB + P_WLO, lane, n0, k0, STR));
                mma_bf16(acc[nb * 2],     ah, bl[0], bl[2]);
                mma_bf16(acc[nb * 2 + 1], ah, bl[1], bl[3]);
            }
        }
        __syncthreads();          // all warps done reading Wlo

        if (m == 0 || m == 2) {
#pragma unroll
            for (int i = 0; i < 8; ++i)
#pragma unroll
                for (int j = 0; j < 4; ++j) keep[i][j] = sigm(acc[i][j]);
        } else if (m == 1 || m == 3) {
            // transpose through smem stage in Wlo region: [d][ij], 144B rows
            __nv_bfloat16* stH = (__nv_bfloat16*)(sm + P_WLO);
            __nv_bfloat16* stL = (__nv_bfloat16*)(sm + P_WLO + 18432);
            const int ijA = m0 + g, ijB = ijA + 8;
#pragma unroll
            for (int nt = 0; nt < 8; ++nt) {
                const int d0 = wn * 64 + nt * 8 + t2;
                float v00 = keep[nt][0] * acc[nt][0];
                float v01 = keep[nt][1] * acc[nt][1];
                float v10 = keep[nt][2] * acc[nt][2];
                float v11 = keep[nt][3] * acc[nt][3];
                __nv_bfloat16 h;
                h = __float2bfloat16(v00); stH[d0 * 72 + ijA] = h;
                stL[d0 * 72 + ijA] = __float2bfloat16(v00 - __bfloat162float(h));
                h = __float2bfloat16(v01); stH[(d0 + 1) * 72 + ijA] = h;
                stL[(d0 + 1) * 72 + ijA] = __float2bfloat16(v01 - __bfloat162float(h));
                h = __float2bfloat16(v10); stH[d0 * 72 + ijB] = h;
                stL[d0 * 72 + ijB] = __float2bfloat16(v10 - __bfloat162float(h));
                h = __float2bfloat16(v11); stH[(d0 + 1) * 72 + ijB] = h;
                stL[(d0 + 1) * 72 + ijB] = __float2bfloat16(v11 - __bfloat162float(h));
            }
            __syncthreads();
            __nv_bfloat16* ph = (m == 1) ? g_ah : g_bh;
            __nv_bfloat16* pl = (m == 1) ? g_al : g_bl;
#pragma unroll
            for (int p = 0; p < 8; ++p) {
                int f = tid + p * 256;          // 0..2047
                int plane = f >> 10, rem = f & 1023;
                int d = rem >> 3, u = rem & 7;
                uint4 v = *(const uint4*)(sm + P_WLO + plane * 18432 + d * 144 + u * 16);
                __nv_bfloat16* gp = plane ? pl : ph;
                *(uint4*)(gp + (size_t)d * NN + base + u * 8) = v;
            }
        } else {
            const size_t ijA = base + m0 + g, ijB = ijA + 8;
#pragma unroll
            for (int nt = 0; nt < 8; ++nt) {
                const int c0 = wn * 64 + nt * 8 + t2;
                *(float2*)&g_gate[ijA * 128 + c0] = make_float2(sigm(acc[nt][0]), sigm(acc[nt][1]));
                *(float2*)&g_gate[ijB * 128 + c0] = make_float2(sigm(acc[nt][2]), sigm(acc[nt][3]));
            }
        }
        __syncthreads();          // Wlo region free for next matrix
    }
}

// ===========================================================================
// Kernel 2: einsum, 128x64 tile, 256 thr (8 warps 2x4, warp = m64 x n16),
// K chunks of 32, cp.async double buffer 2x30KB, occupancy 3 (24 warps/SM).
// buffer: AHI 0 | ALO 10240 | BHI 20480 | BLO 25600  (row stride 40 elems = 80B)
// ===========================================================================
#define E_BUF 30720
#define E_SMEM (2*E_BUF)

__global__ __launch_bounds__(256, 3) void einsum_kernel()
{
    extern __shared__ char sm[];
    const unsigned SB = smem_u32(sm);
    const int tid = threadIdx.x, lane = tid & 31, w = tid >> 5;
    const int g = lane >> 2, t2 = (lane & 3) * 2;
    const int wr = w >> 2, wc = w & 3;
    const int m0w = wr * 64, n0w = wc * 16;
    const int d = blockIdx.z, i0 = blockIdx.y * 128, j0 = blockIdx.x * 64;

    const __nv_bfloat16* pah = g_ah + (size_t)d * NN + (size_t)i0 * Nn;
    const __nv_bfloat16* pal = g_al + (size_t)d * NN + (size_t)i0 * Nn;
    const __nv_bfloat16* pbh = g_bh + (size_t)d * NN + (size_t)j0 * Nn;
    const __nv_bfloat16* pbl = g_bl + (size_t)d * NN + (size_t)j0 * Nn;

    auto stage = [&](int c, int b) {
        const int k0 = c * 32;
        const unsigned dstb = SB + b * E_BUF;
        // A planes: 128 rows x 64B each (4 cp16/row) = 512 cp16/plane
#pragma unroll
        for (int p = 0; p < 2; ++p) {
            const __nv_bfloat16* src = p ? pal : pah;
#pragma unroll
            for (int q = 0; q < 2; ++q) {
                int u = q * 256 + tid;      // 0..511
                int r = u >> 2, sg = u & 3;
                cp16(dstb + p * 10240 + r * 80 + sg * 16,
                     src + (size_t)r * Nn + k0 + sg * 8);
            }
        }
        // B planes: 64 rows = 256 cp16/plane
#pragma unroll
        for (int p = 0; p < 2; ++p) {
            const __nv_bfloat16* src = p ? pbl : pbh;
            int r = tid >> 2, sg = tid & 3;
            cp16(dstb + 20480 + p * 5120 + r * 80 + sg * 16,
                 src + (size_t)r * Nn + k0 + sg * 8);
        }
        CP_COMMIT();
    };

    float acc[8][4];
#pragma unroll
    for (int i = 0; i < 8; ++i)
#pragma unroll
        for (int j = 0; j < 4; ++j) acc[i][j] = 0.f;

    stage(0, 0);
    stage(1, 1);

    for (int c = 0; c < 12; ++c) {
        if (c < 11) { CP_WAIT1(); } else { CP_WAIT0(); }
        __syncthreads();

        const unsigned B = SB + (c & 1) * E_BUF;
#pragma unroll
        for (int ks = 0; ks < 2; ++ks) {
            const int k0 = ks * 16;
            unsigned tb[4];
            ldsm4(tb, ldsm_addr(B + 20480, lane, n0w, k0, 40));
            unsigned bh0a = tb[0], bh0b = tb[2], bh1a = tb[1], bh1b = tb[3];
            ldsm4(tb, ldsm_addr(B + 25600, lane, n0w, k0, 40));
            unsigned bl0a = tb[0], bl0b = tb[2], bl1a = tb[1], bl1b = tb[3];
#pragma unroll
            for (int mt = 0; mt < 4; ++mt) {
                unsigned ah[4], al[4];
                ldsm4(ah, ldsm_addr(B,         lane, m0w + mt * 16, k0, 40));
                ldsm4(al, ldsm_addr(B + 10240, lane, m0w + mt * 16, k0, 40));
                mma_bf16(acc[mt * 2],     ah, bh0a, bh0b);
                mma_bf16(acc[mt * 2],     ah, bl0a, bl0b);
                mma_bf16(acc[mt * 2],     al, bh0a, bh0b);
                mma_bf16(acc[mt * 2 + 1], ah, bh1a, bh1b);
                mma_bf16(acc[mt * 2 + 1], ah, bl1a, bl1b);
                mma_bf16(acc[mt * 2 + 1], al, bh1a, bh1b);
            }
        }
        __syncthreads();
        if (c + 2 < 12) stage(c + 2, c & 1);
    }

    float* plane = g_s + (size_t)d * NN;
#pragma unroll
    for (int mt = 0; mt < 4; ++mt)
#pragma unroll
        for (int nf = 0; nf < 2; ++nf) {
            int row = m0w + mt * 16 + g;
            int col = n0w + nf * 8 + t2;
            float* pr = plane + (size_t)(i0 + row) * Nn + (j0 + col);
            *(float2*)pr            = make_float2(acc[mt * 2 + nf][0], acc[mt * 2 + nf][1]);
            *(float2*)(pr + 8 * Nn) = make_float2(acc[mt * 2 + nf][2], acc[mt * 2 + nf][3]);
        }
}

// ===========================================================================
// Kernel 3: LN(s over d) + Wout + gate. 64-row tiles, 256 thr, occupancy 2.
// s gathered via cp.async into A region, Wout load concurrent at entry.
// smem: A region (34816) | W (69632) | params
// ===========================================================================
#define O_A   0
#define O_W   34816
#define O_G   104448
#define O_B2  104960
#define O_SMEM 105472

__global__ __launch_bounds__(256, 2) void out_kernel(
    const float* __restrict__ gout, const float* __restrict__ bout,
    float* __restrict__ outp)
{
    extern __shared__ char sm[];
    const unsigned SB = smem_u32(sm);
    const int tid = threadIdx.x, lane = tid & 31, w = tid >> 5;
    const int g = lane >> 2, t2 = (lane & 3) * 2;
    const int wm = w >> 1, wn = w & 1;
    const int m0 = wm * 16;
    const size_t base = (size_t)blockIdx.x * 64;

    // group 0: gather s tile [dd][64 fp32] into A region, rows 272B apart
    {
        const float* gs = g_s + base;
#pragma unroll
        for (int p = 0; p < 8; ++p) {
            int f = tid + p * 256;        // 0..2047
            int dd = f >> 4, u = f & 15;
            cp16(SB + O_A + dd * 272 + u * 16, gs + (size_t)dd * NN + u * 4);
        }
        CP_COMMIT();
    }
    // group 1: Wout (matrix index 5) into W region
    {
        const char* srcb = g_wsp + 5 * (size_t)WMAT;
#pragma unroll
        for (int q = 0; q < 17; ++q) {
            int t = tid + q * 256;
            cp16(SB + O_W + t * 16, srcb + (size_t)t * 16);
        }
        CP_COMMIT();
    }

    if (tid < 128) {
        ((float*)(sm + O_G))[tid]  = gout[tid];
        ((float*)(sm + O_B2))[tid] = bout[tid];
    }

    CP_WAIT1();            // gather done (Wout may still be in flight)
    __syncthreads();

    // LN over channels, reading Sf2[dd][row] (stride 68 floats), values buffered
    {
        const int row = tid >> 2, q = tid & 3;
        const float* Sf2 = (const float*)(sm + O_A);
        float sv[32];
        float s = 0.f, s2 = 0.f;
#pragma unroll
        for (int c = 0; c < 32; ++c) {
            float x = Sf2[(q * 32 + c) * 68 + row];
            sv[c] = x; s += x; s2 += x * x;
        }
        s  += __shfl_xor_sync(0xffffffffu, s, 1);  s2 += __shfl_xor_sync(0xffffffffu, s2, 1);
        s  += __shfl_xor_sync(0xffffffffu, s, 2);  s2 += __shfl_xor_sync(0xffffffffu, s2, 2);
        float mu = s * (1.f / 128.f);
        float rs = rsqrtf(fmaf(-mu, mu, s2 * (1.f / 128.f)) + 1e-5f);
        __syncthreads();   // all Sf2 reads complete before overwrite
        const float* G  = (const float*)(sm + O_G);
        const float* Bv = (const float*)(sm + O_B2);
#pragma unroll
        for (int c2 = 0; c2 < 16; ++c2) {
            int c = q * 32 + c2 * 2;
            float x0 = (sv[c2 * 2]     - mu) * rs * G[c]     + Bv[c];
            float x1 = (sv[c2 * 2 + 1] - mu) * rs * G[c + 1] + Bv[c + 1];
            unsigned hi, lo; split2(x0, x1, hi, lo);
            *(unsigned*)(sm + O_A       + (row * STR + c) * 2) = hi;
            *(unsigned*)(sm + O_A + APL + (row * STR + c) * 2) = lo;
        }
    }
    CP_WAIT0();            // Wout resident
    __syncthreads();

    float acc[8][4];
#pragma unroll
    for (int i = 0; i < 8; ++i)
#pragma unroll
        for (int j = 0; j < 4; ++j) acc[i][j] = 0.f;

#pragma unroll
    for (int ks = 0; ks < 8; ++ks) {
        const int k0 = ks * 16;
        unsigned ah[4], al[4];
        ldsm4(ah, ldsm_addr(SB + O_A,       lane, m0, k0, STR));
        ldsm4(al, ldsm_addr(SB + O_A + APL, lane, m0, k0, STR));
#pragma unroll
        for (int nb = 0; nb < 4; ++nb) {
            const int n0 = wn * 64 + nb * 16;
            unsigned bh[4], bl[4];
            ldsm4(bh, ldsm_addr(SB + O_W,          lane, n0, k0, STR));
            ldsm4(bl, ldsm_addr(SB + O_W + WPLANE, lane, n0, k0, STR));
            mma_bf16(acc[nb * 2],     ah, bh[0], bh[2]);
            mma_bf16(acc[nb * 2],     ah, bl[0], bl[2]);
            mma_bf16(acc[nb * 2],     al, bh[0], bh[2]);
            mma_bf16(acc[nb * 2 + 1], ah, bh[1], bh[3]);
            mma_bf16(acc[nb * 2 + 1], ah, bl[1], bl[3]);
            mma_bf16(acc[nb * 2 + 1], al, bh[1], bh[3]);
        }
    }

    const size_t ijA = base + m0 + g, ijB = ijA + 8;
#pragma unroll
    for (int nt = 0; nt < 8; ++nt) {
        const int c0 = wn * 64 + nt * 8 + t2;
        float2 g0 = *(const float2*)&g_gate[ijA * 128 + c0];
        float2 g1 = *(const float2*)&g_gate[ijB * 128 + c0];
        *(float2*)&outp[ijA * 128 + c0] = make_float2(acc[nt][0] * g0.x, acc[nt][1] * g0.y);
        *(float2*)&outp[ijB * 128 + c0] = make_float2(acc[nt][2] * g1.x, acc[nt][3] * g1.y);
    }
}

// ---------------------------------------------------------------------------
extern "C" void kernel_launch(void* const* d_in, const int* in_sizes, int n_in,
                              void* d_out, int out_size)
{
    const float* z    = (const float*)d_in[0];
    const float* gin  = (const float*)d_in[1];
    const float* bin  = (const float*)d_in[2];
    const float* gout = (const float*)d_in[3];
    const float* bout = (const float*)d_in[4];
    const float* Wa1  = (const float*)d_in[5];
    const float* Wa2  = (const float*)d_in[6];
    const float* Wb1  = (const float*)d_in[7];
    const float* Wb2  = (const float*)d_in[8];
    const float* Wg   = (const float*)d_in[9];
    const float* Wout = (const float*)d_in[10];
    float* out = (float*)d_out;

    cudaFuncSetAttribute(proj_kernel,   cudaFuncAttributeMaxDynamicSharedMemorySize, P_SMEM);
    cudaFuncSetAttribute(einsum_kernel, cudaFuncAttributeMaxDynamicSharedMemorySize, E_SMEM);
    cudaFuncSetAttribute(out_kernel,    cudaFuncAttributeMaxDynamicSharedMemorySize, O_SMEM);

    split_weights_kernel<<<192, 256>>>(Wa1, Wa2, Wb1, Wb2, Wg, Wout);
    proj_kernel<<<NN / 64, 256, P_SMEM>>>(z, gin, bin);
    einsum_kernel<<<dim3(Nn / 64, Nn / 128, Cc), 256, E_SMEM>>>();
    out_kernel<<<NN / 64, 256, O_SMEM>>>(gout, bout, out);
}

// round 14
// speedup vs baseline: 1.0448x; 1.0448x over previous
#include <cuda_runtime.h>
#include <cuda_bf16.h>
#include <math.h>

#define Nn 384
#define Cc 128
#define NN (Nn*Nn)   // 147456

// ---------------- global scratch (no allocations allowed) ------------------
__device__ __nv_bfloat16 g_ah[(size_t)Cc*NN];
__device__ __nv_bfloat16 g_al[(size_t)Cc*NN];
__device__ __nv_bfloat16 g_bh[(size_t)Cc*NN];
__device__ __nv_bfloat16 g_bl[(size_t)Cc*NN];
__device__ float g_gate[(size_t)Cc*NN];
__device__ float g_s[(size_t)Cc*NN];

// Pre-split weights as smem tile image: per matrix hi plane [128 x 272B], then lo.
#define WPLANE 34816
#define WMAT   (2*WPLANE)
__device__ __align__(16) char g_wsp[6*WMAT];

// ---------------- helpers ---------------------------------------------------
__device__ __forceinline__ unsigned smem_u32(const void* p) {
    unsigned a;
    asm("{ .reg .u64 t; cvta.to.shared.u64 t, %1; cvt.u32.u64 %0, t; }" : "=r"(a) : "l"(p));
    return a;
}
__device__ __forceinline__ void ldsm4(unsigned r[4], unsigned addr) {
    asm volatile("ldmatrix.sync.aligned.m8n8.x4.shared.b16 {%0,%1,%2,%3}, [%4];"
        : "=r"(r[0]), "=r"(r[1]), "=r"(r[2]), "=r"(r[3]) : "r"(addr));
}
__device__ __forceinline__ void mma_bf16(float c[4], const unsigned a[4], unsigned b0, unsigned b1) {
    asm volatile("mma.sync.aligned.m16n8k16.row.col.f32.bf16.bf16.f32 "
        "{%0,%1,%2,%3}, {%4,%5,%6,%7}, {%8,%9}, {%0,%1,%2,%3};"
        : "+f"(c[0]), "+f"(c[1]), "+f"(c[2]), "+f"(c[3])
        : "r"(a[0]), "r"(a[1]), "r"(a[2]), "r"(a[3]), "r"(b0), "r"(b1));
}
__device__ __forceinline__ unsigned ldsm_addr(unsigned base, int lane, int r0, int c0, int S) {
    int row = r0 + (lane & 7) + ((lane >> 3) & 1) * 8;
    int col = c0 + ((lane >> 4) << 3);
    return base + (unsigned)((row * S + col) * 2);
}
__device__ __forceinline__ void cp16(unsigned dst, const void* src) {
    asm volatile("cp.async.cg.shared.global [%0], [%1], 16;" :: "r"(dst), "l"(src));
}
#define CP_COMMIT() asm volatile("cp.async.commit_group;" ::: "memory")
#define CP_WAIT0()  asm volatile("cp.async.wait_group 0;" ::: "memory")
#define CP_WAIT1()  asm volatile("cp.async.wait_group 1;" ::: "memory")

__device__ __forceinline__ float sigm(float x) { return 1.f / (1.f + __expf(-x)); }

__device__ __forceinline__ void split2(float a, float b, unsigned& hi, unsigned& lo) {
    __nv_bfloat16 ha = __float2bfloat16(a), hb = __float2bfloat16(b);
    float ra = a - __bfloat162float(ha), rb = b - __bfloat162float(hb);
    __nv_bfloat16 la = __float2bfloat16(ra), lb = __float2bfloat16(rb);
    hi = (unsigned)__bfloat16_as_ushort(ha) | ((unsigned)__bfloat16_as_ushort(hb) << 16);
    lo = (unsigned)__bfloat16_as_ushort(la) | ((unsigned)__bfloat16_as_ushort(lb) << 16);
}

#define STR 136      // bf16 row stride for 128-col tiles (272B)
#define APL 17408    // 64-row A plane (64*272)

// ===========================================================================
// Kernel 0: split 6 weight matrices into smem-image layout
// ===========================================================================
__global__ __launch_bounds__(256) void split_weights_kernel(
    const float* __restrict__ Wa1, const float* __restrict__ Wa2,
    const float* __restrict__ Wb1, const float* __restrict__ Wb2,
    const float* __restrict__ Wg,  const float* __restrict__ Wout)
{
    int f = blockIdx.x * 256 + threadIdx.x;       // 6*128*64 = 49152
    int m = f >> 13;
    int rem = f & 8191;
    int h = rem >> 6, c2 = rem & 63;
    const float* W = (m == 0) ? Wa1 : (m == 1) ? Wa2 : (m == 2) ? Wb1 :
                     (m == 3) ? Wb2 : (m == 4) ? Wg : Wout;
    float x0 = W[h * 128 + c2 * 2], x1 = W[h * 128 + c2 * 2 + 1];
    unsigned hi, lo; split2(x0, x1, hi, lo);
    char* basep = g_wsp + (size_t)m * WMAT;
    *(unsigned*)(basep + h * 272 + c2 * 4)          = hi;
    *(unsigned*)(basep + WPLANE + h * 272 + c2 * 4) = lo;
}

// ===========================================================================
// Kernel 1: LN(z) + 5 projections. 64-row tiles, 256 thr, occupancy 2.
// (exact R12 version) smem: A hi/lo (34816) | B/W region (69632) | params
// ===========================================================================
#define P_A   0
#define P_B   34816
#define P_GIN 104448
#define P_BIN 104960
#define P_SMEM 105472

__global__ __launch_bounds__(256, 2) void proj_kernel(
    const float* __restrict__ z,
    const float* __restrict__ gin, const float* __restrict__ bin)
{
    extern __shared__ char sm[];
    const unsigned SB = smem_u32(sm);
    const int tid = threadIdx.x, lane = tid & 31, w = tid >> 5;
    const int g = lane >> 2, t2 = (lane & 3) * 2;
    const int wm = w >> 1, wn = w & 1;
    const int m0 = wm * 16;
    const size_t base = (size_t)blockIdx.x * 64;

    // prefetch W0 into B region immediately (overlaps z load + LN)
    {
#pragma unroll
        for (int q = 0; q < 17; ++q) {
            int t = tid + q * 256;
            cp16(SB + P_B + t * 16, g_wsp + (size_t)t * 16);
        }
        CP_COMMIT();
    }

    if (tid < 128) {
        ((float*)(sm + P_GIN))[tid] = gin[tid];
        ((float*)(sm + P_BIN))[tid] = bin[tid];
    }

    // direct z load: row = tid>>2, cols q*32..q*32+31 (contiguous 128B/thread)
    {
        const int row = tid >> 2, q = tid & 3;
        float zv[32];
        const float4* zp = (const float4*)(z + (base + row) * 128 + q * 32);
#pragma unroll
        for (int i = 0; i < 8; ++i) {
            float4 v = zp[i];
            zv[i * 4]     = v.x; zv[i * 4 + 1] = v.y;
            zv[i * 4 + 2] = v.z; zv[i * 4 + 3] = v.w;
        }
        float s = 0.f, s2 = 0.f;
#pragma unroll
        for (int i = 0; i < 32; ++i) { s += zv[i]; s2 += zv[i] * zv[i]; }
        s  += __shfl_xor_sync(0xffffffffu, s, 1);  s2 += __shfl_xor_sync(0xffffffffu, s2, 1);
        s  += __shfl_xor_sync(0xffffffffu, s, 2);  s2 += __shfl_xor_sync(0xffffffffu, s2, 2);
        float mu = s * (1.f / 128.f);
        float rs = rsqrtf(fmaf(-mu, mu, s2 * (1.f / 128.f)) + 1e-5f);
        __syncthreads();          // params visible
        const float* G  = (const float*)(sm + P_GIN);
        const float* Bv = (const float*)(sm + P_BIN);
#pragma unroll
        for (int c2 = 0; c2 < 16; ++c2) {
            int c = q * 32 + c2 * 2;
            float x0 = (zv[c2 * 2]     - mu) * rs * G[c]     + Bv[c];
            float x1 = (zv[c2 * 2 + 1] - mu) * rs * G[c + 1] + Bv[c + 1];
            unsigned hi, lo; split2(x0, x1, hi, lo);
            *(unsigned*)(sm + P_A       + (row * STR + c) * 2) = hi;
            *(unsigned*)(sm + P_A + APL + (row * STR + c) * 2) = lo;
        }
    }

    float keep[8][4];

    for (int m = 0; m < 5; ++m) {
        if (m > 0) {      // W0 already issued at entry
            const char* srcb = g_wsp + (size_t)m * WMAT;
#pragma unroll
            for (int q = 0; q < 17; ++q) {
                int t = tid + q * 256;
                cp16(SB + P_B + t * 16, srcb + (size_t)t * 16);
            }
            CP_COMMIT();
        }
        CP_WAIT0();
        __syncthreads();          // W[m] + A tiles visible to all

        float acc[8][4];
#pragma unroll
        for (int i = 0; i < 8; ++i)
#pragma unroll
            for (int j = 0; j < 4; ++j) acc[i][j] = 0.f;

#pragma unroll
        for (int ks = 0; ks < 8; ++ks) {
            const int k0 = ks * 16;
            unsigned ah[4], al[4];
            ldsm4(ah, ldsm_addr(SB + P_A,       lane, m0, k0, STR));
            ldsm4(al, ldsm_addr(SB + P_A + APL, lane, m0, k0, STR));
#pragma unroll
            for (int nb = 0; nb < 4; ++nb) {
                const int n0 = wn * 64 + nb * 16;
                unsigned bh[4], bl[4];
                ldsm4(bh, ldsm_addr(SB + P_B,          lane, n0, k0, STR));
                ldsm4(bl, ldsm_addr(SB + P_B + WPLANE, lane, n0, k0, STR));
                mma_bf16(acc[nb * 2],     ah, bh[0], bh[2]);
                mma_bf16(acc[nb * 2],     ah, bl[0], bl[2]);
                mma_bf16(acc[nb * 2],     al, bh[0], bh[2]);
                mma_bf16(acc[nb * 2 + 1], ah, bh[1], bh[3]);
                mma_bf16(acc[nb * 2 + 1], ah, bl[1], bl[3]);
                mma_bf16(acc[nb * 2 + 1], al, bh[1], bh[3]);
            }
        }
        __syncthreads();   // all warps done reading B

        if (m == 0 || m == 2) {
#pragma unroll
            for (int i = 0; i < 8; ++i)
#pragma unroll
                for (int j = 0; j < 4; ++j) keep[i][j] = sigm(acc[i][j]);
        } else if (m == 1 || m == 3) {
            // transpose through smem stage in B region: [d][ij], 144B rows
            __nv_bfloat16* stH = (__nv_bfloat16*)(sm + P_B);
            __nv_bfloat16* stL = (__nv_bfloat16*)(sm + P_B + 18432);
            const int ijA = m0 + g, ijB = ijA + 8;
#pragma unroll
            for (int nt = 0; nt < 8; ++nt) {
                const int d0 = wn * 64 + nt * 8 + t2;
                float v00 = keep[nt][0] * acc[nt][0];
                float v01 = keep[nt][1] * acc[nt][1];
                float v10 = keep[nt][2] * acc[nt][2];
                float v11 = keep[nt][3] * acc[nt][3];
                __nv_bfloat16 h;
                h = __float2bfloat16(v00); stH[d0 * 72 + ijA] = h;
                stL[d0 * 72 + ijA] = __float2bfloat16(v00 - __bfloat162float(h));
                h = __float2bfloat16(v01); stH[(d0 + 1) * 72 + ijA] = h;
                stL[(d0 + 1) * 72 + ijA] = __float2bfloat16(v01 - __bfloat162float(h));
                h = __float2bfloat16(v10); stH[d0 * 72 + ijB] = h;
                stL[d0 * 72 + ijB] = __float2bfloat16(v10 - __bfloat162float(h));
                h = __float2bfloat16(v11); stH[(d0 + 1) * 72 + ijB] = h;
                stL[(d0 + 1) * 72 + ijB] = __float2bfloat16(v11 - __bfloat162float(h));
            }
            __syncthreads();
            __nv_bfloat16* ph = (m == 1) ? g_ah : g_bh;
            __nv_bfloat16* pl = (m == 1) ? g_al : g_bl;
#pragma unroll
            for (int p = 0; p < 8; ++p) {
                int f = tid + p * 256;          // 0..2047
                int plane = f >> 10, rem = f & 1023;
                int d = rem >> 3, u = rem & 7;
                uint4 v = *(const uint4*)(sm + P_B + plane * 18432 + d * 144 + u * 16);
                __nv_bfloat16* gp = plane ? pl : ph;
                *(uint4*)(gp + (size_t)d * NN + base + u * 8) = v;
            }
        } else {
            const size_t ijA = base + m0 + g, ijB = ijA + 8;
#pragma unroll
            for (int nt = 0; nt < 8; ++nt) {
                const int c0 = wn * 64 + nt * 8 + t2;
                *(float2*)&g_gate[ijA * 128 + c0] = make_float2(sigm(acc[nt][0]), sigm(acc[nt][1]));
                *(float2*)&g_gate[ijB * 128 + c0] = make_float2(sigm(acc[nt][2]), sigm(acc[nt][3]));
            }
        }
        __syncthreads();   // B region free for next matrix
    }
}

// ===========================================================================
// Kernel 2: einsum, 128x128 tile, 512 thr (16 warps 2x8, warp = m64 x n16),
// K chunks of 32, cp.async double buffer 2x32KB with 64B swizzled rows,
// occupancy 2 -> 32 warps/SM.
// stage: AHI 0 | ALO 8192 | BHI 16384 | BLO 24576 (each 128 rows x 64B)
// swizzle: 16B chunk index ^= (row>>1)&3  (conflict-free for cp16 + ldsm)
// ===========================================================================
#define E_BUF 32768
#define E_SMEM (2*E_BUF)

__global__ __launch_bounds__(512, 2) void einsum_kernel()
{
    extern __shared__ char sm[];
    const unsigned SB = smem_u32(sm);
    const int tid = threadIdx.x, lane = tid & 31, w = tid >> 5;
    const int g = lane >> 2, t2 = (lane & 3) * 2;
    const int wr = w >> 3, wc = w & 7;          // 2 x 8 warp grid
    const int m0w = wr * 64, n0w = wc * 16;
    const int d = blockIdx.z, i0 = blockIdx.y * 128, j0 = blockIdx.x * 128;

    const __nv_bfloat16* pah = g_ah + (size_t)d * NN + (size_t)i0 * Nn;
    const __nv_bfloat16* pal = g_al + (size_t)d * NN + (size_t)i0 * Nn;
    const __nv_bfloat16* pbh = g_bh + (size_t)d * NN + (size_t)j0 * Nn;
    const __nv_bfloat16* pbl = g_bl + (size_t)d * NN + (size_t)j0 * Nn;

    // swizzled ldsm address: k16 block at kk within 32-wide rows
    auto eaddr = [&](unsigned pbase, int r0, int kk) -> unsigned {
        int row = r0 + (lane & 7) + ((lane >> 3) & 1) * 8;
        int ch = (kk >> 3) + ((lane >> 4) & 1);
        ch ^= (row >> 1) & 3;
        return pbase + (unsigned)(row * 64 + ch * 16);
    };

    auto stage = [&](int c, int b) {
        const int k0 = c * 32;
        const unsigned dstb = SB + b * E_BUF;
#pragma unroll
        for (int q = 0; q < 4; ++q) {
            int u = q * 512 + tid;            // 0..2047
            int p = u >> 9, rem = u & 511;
            int r = rem >> 2, sg = rem & 3;
            int sw = sg ^ ((r >> 1) & 3);
            const __nv_bfloat16* src = (p == 0) ? pah : (p == 1) ? pal : (p == 2) ? pbh : pbl;
            cp16(dstb + p * 8192 + r * 64 + sw * 16,
                 src + (size_t)r * Nn + k0 + sg * 8);
        }
        CP_COMMIT();
    };

    float acc[8][4];
#pragma unroll
    for (int i = 0; i < 8; ++i)
#pragma unroll
        for (int j = 0; j < 4; ++j) acc[i][j] = 0.f;

    stage(0, 0);
    stage(1, 1);

    for (int c = 0; c < 12; ++c) {
        if (c < 11) { CP_WAIT1(); } else { CP_WAIT0(); }
        __syncthreads();

        const unsigned B = SB + (c & 1) * E_BUF;
#pragma unroll
        for (int ks = 0; ks < 2; ++ks) {
            const int kk = ks * 16;
            unsigned tb[4];
            ldsm4(tb, eaddr(B + 16384, n0w, kk));
            unsigned bhA0 = tb[0], bhA1 = tb[2], bhB0 = tb[1], bhB1 = tb[3];
            ldsm4(tb, eaddr(B + 24576, n0w, kk));
            unsigned blA0 = tb[0], blA1 = tb[2], blB0 = tb[1], blB1 = tb[3];
#pragma unroll
            for (int mt = 0; mt < 4; ++mt) {
                unsigned ah[4], al[4];
                ldsm4(ah, eaddr(B,        m0w + mt * 16, kk));
                ldsm4(al, eaddr(B + 8192, m0w + mt * 16, kk));
                mma_bf16(acc[mt * 2],     ah, bhA0, bhA1);
                mma_bf16(acc[mt * 2],     ah, blA0, blA1);
                mma_bf16(acc[mt * 2],     al, bhA0, bhA1);
                mma_bf16(acc[mt * 2 + 1], ah, bhB0, bhB1);
                mma_bf16(acc[mt * 2 + 1], ah, blB0, blB1);
                mma_bf16(acc[mt * 2 + 1], al, bhB0, bhB1);
            }
        }
        __syncthreads();
        if (c + 2 < 12) stage(c + 2, c & 1);
    }

    float* plane = g_s + (size_t)d * NN;
#pragma unroll
    for (int mt = 0; mt < 4; ++mt)
#pragma unroll
        for (int nf = 0; nf < 2; ++nf) {
            int row = m0w + mt * 16 + g;
            int col = n0w + nf * 8 + t2;
            float* pr = plane + (size_t)(i0 + row) * Nn + (j0 + col);
            *(float2*)pr            = make_float2(acc[mt * 2 + nf][0], acc[mt * 2 + nf][1]);
            *(float2*)(pr + 8 * Nn) = make_float2(acc[mt * 2 + nf][2], acc[mt * 2 + nf][3]);
        }
}

// ===========================================================================
// Kernel 3: LN(s over d) + Wout + gate. 64-row tiles, 256 thr, occupancy 2.
// (exact R12 version) smem: A region (34816) | W (69632) | params
// ===========================================================================
#define O_A   0
#define O_W   34816
#define O_G   104448
#define O_B2  104960
#define O_SMEM 105472

__global__ __launch_bounds__(256, 2) void out_kernel(
    const float* __restrict__ gout, const float* __restrict__ bout,
    float* __restrict__ outp)
{
    extern __shared__ char sm[];
    const unsigned SB = smem_u32(sm);
    const int tid = threadIdx.x, lane = tid & 31, w = tid >> 5;
    const int g = lane >> 2, t2 = (lane & 3) * 2;
    const int wm = w >> 1, wn = w & 1;
    const int m0 = wm * 16;
    const size_t base = (size_t)blockIdx.x * 64;

    // group 0: gather s tile [dd][64 fp32] into A region, rows 272B apart
    {
        const float* gs = g_s + base;
#pragma unroll
        for (int p = 0; p < 8; ++p) {
            int f = tid + p * 256;        // 0..2047
            int dd = f >> 4, u = f & 15;
            cp16(SB + O_A + dd * 272 + u * 16, gs + (size_t)dd * NN + u * 4);
        }
        CP_COMMIT();
    }
    // group 1: Wout (matrix index 5) into W region
    {
        const char* srcb = g_wsp + 5 * (size_t)WMAT;
#pragma unroll
        for (int q = 0; q < 17; ++q) {
            int t = tid + q * 256;
            cp16(SB + O_W + t * 16, srcb + (size_t)t * 16);
        }
        CP_COMMIT();
    }

    if (tid < 128) {
        ((float*)(sm + O_G))[tid]  = gout[tid];
        ((float*)(sm + O_B2))[tid] = bout[tid];
    }

    CP_WAIT1();            // gather done (Wout may still be in flight)
    __syncthreads();

    // LN over channels, reading Sf2[dd][row] (stride 68 floats), values buffered
    {
        const int row = tid >> 2, q = tid & 3;
        const float* Sf2 = (const float*)(sm + O_A);
        float sv[32];
        float s = 0.f, s2 = 0.f;
#pragma unroll
        for (int c = 0; c < 32; ++c) {
            float x = Sf2[(q * 32 + c) * 68 + row];
            sv[c] = x; s += x; s2 += x * x;
        }
        s  += __shfl_xor_sync(0xffffffffu, s, 1);  s2 += __shfl_xor_sync(0xffffffffu, s2, 1);
        s  += __shfl_xor_sync(0xffffffffu, s, 2);  s2 += __shfl_xor_sync(0xffffffffu, s2, 2);
        float mu = s * (1.f / 128.f);
        float rs = rsqrtf(fmaf(-mu, mu, s2 * (1.f / 128.f)) + 1e-5f);
        __syncthreads();   // all Sf2 reads complete before overwrite
        const float* G  = (const float*)(sm + O_G);
        const float* Bv = (const float*)(sm + O_B2);
#pragma unroll
        for (int c2 = 0; c2 < 16; ++c2) {
            int c = q * 32 + c2 * 2;
            float x0 = (sv[c2 * 2]     - mu) * rs * G[c]     + Bv[c];
            float x1 = (sv[c2 * 2 + 1] - mu) * rs * G[c + 1] + Bv[c + 1];
            unsigned hi, lo; split2(x0, x1, hi, lo);
            *(unsigned*)(sm + O_A       + (row * STR + c) * 2) = hi;
            *(unsigned*)(sm + O_A + APL + (row * STR + c) * 2) = lo;
        }
    }
    CP_WAIT0();            // Wout resident
    __syncthreads();

    float acc[8][4];
#pragma unroll
    for (int i = 0; i < 8; ++i)
#pragma unroll
        for (int j = 0; j < 4; ++j) acc[i][j] = 0.f;

#pragma unroll
    for (int ks = 0; ks < 8; ++ks) {
        const int k0 = ks * 16;
        unsigned ah[4], al[4];
        ldsm4(ah, ldsm_addr(SB + O_A,       lane, m0, k0, STR));
        ldsm4(al, ldsm_addr(SB + O_A + APL, lane, m0, k0, STR));
#pragma unroll
        for (int nb = 0; nb < 4; ++nb) {
            const int n0 = wn * 64 + nb * 16;
            unsigned bh[4], bl[4];
            ldsm4(bh, ldsm_addr(SB + O_W,          lane, n0, k0, STR));
            ldsm4(bl, ldsm_addr(SB + O_W + WPLANE, lane, n0, k0, STR));
            mma_bf16(acc[nb * 2],     ah, bh[0], bh[2]);
            mma_bf16(acc[nb * 2],     ah, bl[0], bl[2]);
            mma_bf16(acc[nb * 2],     al, bh[0], bh[2]);
            mma_bf16(acc[nb * 2 + 1], ah, bh[1], bh[3]);
            mma_bf16(acc[nb * 2 + 1], ah, bl[1], bl[3]);
            mma_bf16(acc[nb * 2 + 1], al, bh[1], bh[3]);
        }
    }

    const size_t ijA = base + m0 + g, ijB = ijA + 8;
#pragma unroll
    for (int nt = 0; nt < 8; ++nt) {
        const int c0 = wn * 64 + nt * 8 + t2;
        float2 g0 = *(const float2*)&g_gate[ijA * 128 + c0];
        float2 g1 = *(const float2*)&g_gate[ijB * 128 + c0];
        *(float2*)&outp[ijA * 128 + c0] = make_float2(acc[nt][0] * g0.x, acc[nt][1] * g0.y);
        *(float2*)&outp[ijB * 128 + c0] = make_float2(acc[nt][2] * g1.x, acc[nt][3] * g1.y);
    }
}

// ---------------------------------------------------------------------------
extern "C" void kernel_launch(void* const* d_in, const int* in_sizes, int n_in,
                              void* d_out, int out_size)
{
    const float* z    = (const float*)d_in[0];
    const float* gin  = (const float*)d_in[1];
    const float* bin  = (const float*)d_in[2];
    const float* gout = (const float*)d_in[3];
    const float* bout = (const float*)d_in[4];
    const float* Wa1  = (const float*)d_in[5];
    const float* Wa2  = (const float*)d_in[6];
    const float* Wb1  = (const float*)d_in[7];
    const float* Wb2  = (const float*)d_in[8];
    const float* Wg   = (const float*)d_in[9];
    const float* Wout = (const float*)d_in[10];
    float* out = (float*)d_out;

    cudaFuncSetAttribute(proj_kernel,   cudaFuncAttributeMaxDynamicSharedMemorySize, P_SMEM);
    cudaFuncSetAttribute(einsum_kernel, cudaFuncAttributeMaxDynamicSharedMemorySize, E_SMEM);
    cudaFuncSetAttribute(out_kernel,    cudaFuncAttributeMaxDynamicSharedMemorySize, O_SMEM);

    split_weights_kernel<<<192, 256>>>(Wa1, Wa2, Wb1, Wb2, Wg, Wout);
    proj_kernel<<<NN / 64, 256, P_SMEM>>>(z, gin, bin);
    einsum_kernel<<<dim3(Nn / 128, Nn / 128, Cc), 512, E_SMEM>>>();
    out_kernel<<<NN / 64, 256, O_SMEM>>>(gout, bout, out);
}

// round 15
// speedup vs baseline: 1.0491x; 1.0042x over previous
#include <cuda_runtime.h>
#include <cuda_bf16.h>
#include <math.h>

#define Nn 384
#define Cc 128
#define NN (Nn*Nn)   // 147456

// ---------------- global scratch (no allocations allowed) ------------------
__device__ __nv_bfloat16 g_ah[(size_t)Cc*NN];
__device__ __nv_bfloat16 g_al[(size_t)Cc*NN];
__device__ __nv_bfloat16 g_bh[(size_t)Cc*NN];
__device__ __nv_bfloat16 g_bl[(size_t)Cc*NN];
__device__ float g_gate[(size_t)Cc*NN];
__device__ float g_s[(size_t)Cc*NN];

// Pre-split weights as smem tile image: per matrix hi plane [128 x 272B], then lo.
#define WPLANE 34816
#define WMAT   (2*WPLANE)
__device__ __align__(16) char g_wsp[6*WMAT];

// ---------------- helpers ---------------------------------------------------
__device__ __forceinline__ unsigned smem_u32(const void* p) {
    unsigned a;
    asm("{ .reg .u64 t; cvta.to.shared.u64 t, %1; cvt.u32.u64 %0, t; }" : "=r"(a) : "l"(p));
    return a;
}
__device__ __forceinline__ void ldsm4(unsigned r[4], unsigned addr) {
    asm volatile("ldmatrix.sync.aligned.m8n8.x4.shared.b16 {%0,%1,%2,%3}, [%4];"
        : "=r"(r[0]), "=r"(r[1]), "=r"(r[2]), "=r"(r[3]) : "r"(addr));
}
__device__ __forceinline__ void mma_bf16(float c[4], const unsigned a[4], unsigned b0, unsigned b1) {
    asm volatile("mma.sync.aligned.m16n8k16.row.col.f32.bf16.bf16.f32 "
        "{%0,%1,%2,%3}, {%4,%5,%6,%7}, {%8,%9}, {%0,%1,%2,%3};"
        : "+f"(c[0]), "+f"(c[1]), "+f"(c[2]), "+f"(c[3])
        : "r"(a[0]), "r"(a[1]), "r"(a[2]), "r"(a[3]), "r"(b0), "r"(b1));
}
__device__ __forceinline__ unsigned ldsm_addr(unsigned base, int lane, int r0, int c0, int S) {
    int row = r0 + (lane & 7) + ((lane >> 3) & 1) * 8;
    int col = c0 + ((lane >> 4) << 3);
    return base + (unsigned)((row * S + col) * 2);
}
__device__ __forceinline__ void cp16(unsigned dst, const void* src) {
    asm volatile("cp.async.cg.shared.global [%0], [%1], 16;" :: "r"(dst), "l"(src));
}
#define CP_COMMIT() asm volatile("cp.async.commit_group;" ::: "memory")
#define CP_WAIT0()  asm volatile("cp.async.wait_group 0;" ::: "memory")
#define CP_WAIT1()  asm volatile("cp.async.wait_group 1;" ::: "memory")

__device__ __forceinline__ float sigm(float x) { return 1.f / (1.f + __expf(-x)); }

__device__ __forceinline__ void split2(float a, float b, unsigned& hi, unsigned& lo) {
    __nv_bfloat16 ha = __float2bfloat16(a), hb = __float2bfloat16(b);
    float ra = a - __bfloat162float(ha), rb = b - __bfloat162float(hb);
    __nv_bfloat16 la = __float2bfloat16(ra), lb = __float2bfloat16(rb);
    hi = (unsigned)__bfloat16_as_ushort(ha) | ((unsigned)__bfloat16_as_ushort(hb) << 16);
    lo = (unsigned)__bfloat16_as_ushort(la) | ((unsigned)__bfloat16_as_ushort(lb) << 16);
}

#define STR 136      // bf16 row stride for 128-col tiles (272B)
#define APL 17408    // 64-row A plane (64*272)

// ===========================================================================
// Kernel 0: split 6 weight matrices into smem-image layout
// ===========================================================================
__global__ __launch_bounds__(256) void split_weights_kernel(
    const float* __restrict__ Wa1, const float* __restrict__ Wa2,
    const float* __restrict__ Wb1, const float* __restrict__ Wb2,
    const float* __restrict__ Wg,  const float* __restrict__ Wout)
{
    int f = blockIdx.x * 256 + threadIdx.x;       // 6*128*64 = 49152
    int m = f >> 13;
    int rem = f & 8191;
    int h = rem >> 6, c2 = rem & 63;
    const float* W = (m == 0) ? Wa1 : (m == 1) ? Wa2 : (m == 2) ? Wb1 :
                     (m == 3) ? Wb2 : (m == 4) ? Wg : Wout;
    float x0 = W[h * 128 + c2 * 2], x1 = W[h * 128 + c2 * 2 + 1];
    unsigned hi, lo; split2(x0, x1, hi, lo);
    char* basep = g_wsp + (size_t)m * WMAT;
    *(unsigned*)(basep + h * 272 + c2 * 4)          = hi;
    *(unsigned*)(basep + WPLANE + h * 272 + c2 * 4) = lo;
}

// ===========================================================================
// Kernel 1: LN(z) + 5 projections. 64-row tiles, 256 thr, occupancy 2.
// (exact R12/R14 version)
// ===========================================================================
#define P_A   0
#define P_B   34816
#define P_GIN 104448
#define P_BIN 104960
#define P_SMEM 105472

__global__ __launch_bounds__(256, 2) void proj_kernel(
    const float* __restrict__ z,
    const float* __restrict__ gin, const float* __restrict__ bin)
{
    extern __shared__ char sm[];
    const unsigned SB = smem_u32(sm);
    const int tid = threadIdx.x, lane = tid & 31, w = tid >> 5;
    const int g = lane >> 2, t2 = (lane & 3) * 2;
    const int wm = w >> 1, wn = w & 1;
    const int m0 = wm * 16;
    const size_t base = (size_t)blockIdx.x * 64;

    // prefetch W0 into B region immediately (overlaps z load + LN)
    {
#pragma unroll
        for (int q = 0; q < 17; ++q) {
            int t = tid + q * 256;
            cp16(SB + P_B + t * 16, g_wsp + (size_t)t * 16);
        }
        CP_COMMIT();
    }

    if (tid < 128) {
        ((float*)(sm + P_GIN))[tid] = gin[tid];
        ((float*)(sm + P_BIN))[tid] = bin[tid];
    }

    // direct z load: row = tid>>2, cols q*32..q*32+31 (contiguous 128B/thread)
    {
        const int row = tid >> 2, q = tid & 3;
        float zv[32];
        const float4* zp = (const float4*)(z + (base + row) * 128 + q * 32);
#pragma unroll
        for (int i = 0; i < 8; ++i) {
            float4 v = zp[i];
            zv[i * 4]     = v.x; zv[i * 4 + 1] = v.y;
            zv[i * 4 + 2] = v.z; zv[i * 4 + 3] = v.w;
        }
        float s = 0.f, s2 = 0.f;
#pragma unroll
        for (int i = 0; i < 32; ++i) { s += zv[i]; s2 += zv[i] * zv[i]; }
        s  += __shfl_xor_sync(0xffffffffu, s, 1);  s2 += __shfl_xor_sync(0xffffffffu, s2, 1);
        s  += __shfl_xor_sync(0xffffffffu, s, 2);  s2 += __shfl_xor_sync(0xffffffffu, s2, 2);
        float mu = s * (1.f / 128.f);
        float rs = rsqrtf(fmaf(-mu, mu, s2 * (1.f / 128.f)) + 1e-5f);
        __syncthreads();          // params visible
        const float* G  = (const float*)(sm + P_GIN);
        const float* Bv = (const float*)(sm + P_BIN);
#pragma unroll
        for (int c2 = 0; c2 < 16; ++c2) {
            int c = q * 32 + c2 * 2;
            float x0 = (zv[c2 * 2]     - mu) * rs * G[c]     + Bv[c];
            float x1 = (zv[c2 * 2 + 1] - mu) * rs * G[c + 1] + Bv[c + 1];
            unsigned hi, lo; split2(x0, x1, hi, lo);
            *(unsigned*)(sm + P_A       + (row * STR + c) * 2) = hi;
            *(unsigned*)(sm + P_A + APL + (row * STR + c) * 2) = lo;
        }
    }

    float keep[8][4];

    for (int m = 0; m < 5; ++m) {
        if (m > 0) {      // W0 already issued at entry
            const char* srcb = g_wsp + (size_t)m * WMAT;
#pragma unroll
            for (int q = 0; q < 17; ++q) {
                int t = tid + q * 256;
                cp16(SB + P_B + t * 16, srcb + (size_t)t * 16);
            }
            CP_COMMIT();
        }
        CP_WAIT0();
        __syncthreads();          // W[m] + A tiles visible to all

        float acc[8][4];
#pragma unroll
        for (int i = 0; i < 8; ++i)
#pragma unroll
            for (int j = 0; j < 4; ++j) acc[i][j] = 0.f;

#pragma unroll
        for (int ks = 0; ks < 8; ++ks) {
            const int k0 = ks * 16;
            unsigned ah[4], al[4];
            ldsm4(ah, ldsm_addr(SB + P_A,       lane, m0, k0, STR));
            ldsm4(al, ldsm_addr(SB + P_A + APL, lane, m0, k0, STR));
#pragma unroll
            for (int nb = 0; nb < 4; ++nb) {
                const int n0 = wn * 64 + nb * 16;
                unsigned bh[4], bl[4];
                ldsm4(bh, ldsm_addr(SB + P_B,          lane, n0, k0, STR));
                ldsm4(bl, ldsm_addr(SB + P_B + WPLANE, lane, n0, k0, STR));
                mma_bf16(acc[nb * 2],     ah, bh[0], bh[2]);
                mma_bf16(acc[nb * 2],     ah, bl[0], bl[2]);
                mma_bf16(acc[nb * 2],     al, bh[0], bh[2]);
                mma_bf16(acc[nb * 2 + 1], ah, bh[1], bh[3]);
                mma_bf16(acc[nb * 2 + 1], ah, bl[1], bl[3]);
                mma_bf16(acc[nb * 2 + 1], al, bh[1], bh[3]);
            }
        }
        __syncthreads();   // all warps done reading B

        if (m == 0 || m == 2) {
#pragma unroll
            for (int i = 0; i < 8; ++i)
#pragma unroll
                for (int j = 0; j < 4; ++j) keep[i][j] = sigm(acc[i][j]);
        } else if (m == 1 || m == 3) {
            // transpose through smem stage in B region: [d][ij], 144B rows
            __nv_bfloat16* stH = (__nv_bfloat16*)(sm + P_B);
            __nv_bfloat16* stL = (__nv_bfloat16*)(sm + P_B + 18432);
            const int ijA = m0 + g, ijB = ijA + 8;
#pragma unroll
            for (int nt = 0; nt < 8; ++nt) {
                const int d0 = wn * 64 + nt * 8 + t2;
                float v00 = keep[nt][0] * acc[nt][0];
                float v01 = keep[nt][1] * acc[nt][1];
                float v10 = keep[nt][2] * acc[nt][2];
                float v11 = keep[nt][3] * acc[nt][3];
                __nv_bfloat16 h;
                h = __float2bfloat16(v00); stH[d0 * 72 + ijA] = h;
                stL[d0 * 72 + ijA] = __float2bfloat16(v00 - __bfloat162float(h));
                h = __float2bfloat16(v01); stH[(d0 + 1) * 72 + ijA] = h;
                stL[(d0 + 1) * 72 + ijA] = __float2bfloat16(v01 - __bfloat162float(h));
                h = __float2bfloat16(v10); stH[d0 * 72 + ijB] = h;
                stL[d0 * 72 + ijB] = __float2bfloat16(v10 - __bfloat162float(h));
                h = __float2bfloat16(v11); stH[(d0 + 1) * 72 + ijB] = h;
                stL[(d0 + 1) * 72 + ijB] = __float2bfloat16(v11 - __bfloat162float(h));
            }
            __syncthreads();
            __nv_bfloat16* ph = (m == 1) ? g_ah : g_bh;
            __nv_bfloat16* pl = (m == 1) ? g_al : g_bl;
#pragma unroll
            for (int p = 0; p < 8; ++p) {
                int f = tid + p * 256;          // 0..2047
                int plane = f >> 10, rem = f & 1023;
                int d = rem >> 3, u = rem & 7;
                uint4 v = *(const uint4*)(sm + P_B + plane * 18432 + d * 144 + u * 16);
                __nv_bfloat16* gp = plane ? pl : ph;
                *(uint4*)(gp + (size_t)d * NN + base + u * 8) = v;
            }
        } else {
            const size_t ijA = base + m0 + g, ijB = ijA + 8;
#pragma unroll
            for (int nt = 0; nt < 8; ++nt) {
                const int c0 = wn * 64 + nt * 8 + t2;
                *(float2*)&g_gate[ijA * 128 + c0] = make_float2(sigm(acc[nt][0]), sigm(acc[nt][1]));
                *(float2*)&g_gate[ijB * 128 + c0] = make_float2(sigm(acc[nt][2]), sigm(acc[nt][3]));
            }
        }
        __syncthreads();   // B region free for next matrix
    }
}

// ===========================================================================
// Kernel 2: einsum (exact R14 version): 128x128 tile, 512 thr, K32 chunks,
// double buffer 2x32KB with 64B swizzled rows, occupancy 2.
// ===========================================================================
#define E_BUF 32768
#define E_SMEM (2*E_BUF)

__global__ __launch_bounds__(512, 2) void einsum_kernel()
{
    extern __shared__ char sm[];
    const unsigned SB = smem_u32(sm);
    const int tid = threadIdx.x, lane = tid & 31, w = tid >> 5;
    const int g = lane >> 2, t2 = (lane & 3) * 2;
    const int wr = w >> 3, wc = w & 7;          // 2 x 8 warp grid
    const int m0w = wr * 64, n0w = wc * 16;
    const int d = blockIdx.z, i0 = blockIdx.y * 128, j0 = blockIdx.x * 128;

    const __nv_bfloat16* pah = g_ah + (size_t)d * NN + (size_t)i0 * Nn;
    const __nv_bfloat16* pal = g_al + (size_t)d * NN + (size_t)i0 * Nn;
    const __nv_bfloat16* pbh = g_bh + (size_t)d * NN + (size_t)j0 * Nn;
    const __nv_bfloat16* pbl = g_bl + (size_t)d * NN + (size_t)j0 * Nn;

    auto eaddr = [&](unsigned pbase, int r0, int kk) -> unsigned {
        int row = r0 + (lane & 7) + ((lane >> 3) & 1) * 8;
        int ch = (kk >> 3) + ((lane >> 4) & 1);
        ch ^= (row >> 1) & 3;
        return pbase + (unsigned)(row * 64 + ch * 16);
    };

    auto stage = [&](int c, int b) {
        const int k0 = c * 32;
        const unsigned dstb = SB + b * E_BUF;
#pragma unroll
        for (int q = 0; q < 4; ++q) {
            int u = q * 512 + tid;            // 0..2047
            int p = u >> 9, rem = u & 511;
            int r = rem >> 2, sg = rem & 3;
            int sw = sg ^ ((r >> 1) & 3);
            const __nv_bfloat16* src = (p == 0) ? pah : (p == 1) ? pal : (p == 2) ? pbh : pbl;
            cp16(dstb + p * 8192 + r * 64 + sw * 16,
                 src + (size_t)r * Nn + k0 + sg * 8);
        }
        CP_COMMIT();
    };

    float acc[8][4];
#pragma unroll
    for (int i = 0; i < 8; ++i)
#pragma unroll
        for (int j = 0; j < 4; ++j) acc[i][j] = 0.f;

    stage(0, 0);
    stage(1, 1);

    for (int c = 0; c < 12; ++c) {
        if (c < 11) { CP_WAIT1(); } else { CP_WAIT0(); }
        __syncthreads();

        const unsigned B = SB + (c & 1) * E_BUF;
#pragma unroll
        for (int ks = 0; ks < 2; ++ks) {
            const int kk = ks * 16;
            unsigned tb[4];
            ldsm4(tb, eaddr(B + 16384, n0w, kk));
            unsigned bhA0 = tb[0], bhA1 = tb[2], bhB0 = tb[1], bhB1 = tb[3];
            ldsm4(tb, eaddr(B + 24576, n0w, kk));
            unsigned blA0 = tb[0], blA1 = tb[2], blB0 = tb[1], blB1 = tb[3];
#pragma unroll
            for (int mt = 0; mt < 4; ++mt) {
                unsigned ah[4], al[4];
                ldsm4(ah, eaddr(B,        m0w + mt * 16, kk));
                ldsm4(al, eaddr(B + 8192, m0w + mt * 16, kk));
                mma_bf16(acc[mt * 2],     ah, bhA0, bhA1);
                mma_bf16(acc[mt * 2],     ah, blA0, blA1);
                mma_bf16(acc[mt * 2],     al, bhA0, bhA1);
                mma_bf16(acc[mt * 2 + 1], ah, bhB0, bhB1);
                mma_bf16(acc[mt * 2 + 1], ah, blB0, blB1);
                mma_bf16(acc[mt * 2 + 1], al, bhB0, bhB1);
            }
        }
        __syncthreads();
        if (c + 2 < 12) stage(c + 2, c & 1);
    }

    float* plane = g_s + (size_t)d * NN;
#pragma unroll
    for (int mt = 0; mt < 4; ++mt)
#pragma unroll
        for (int nf = 0; nf < 2; ++nf) {
            int row = m0w + mt * 16 + g;
            int col = n0w + nf * 8 + t2;
            float* pr = plane + (size_t)(i0 + row) * Nn + (j0 + col);
            *(float2*)pr            = make_float2(acc[mt * 2 + nf][0], acc[mt * 2 + nf][1]);
            *(float2*)(pr + 8 * Nn) = make_float2(acc[mt * 2 + nf][2], acc[mt * 2 + nf][3]);
        }
}

// ===========================================================================
// Kernel 3: LN(s over d) + Wout + gate. 64-row tiles, 256 thr, OCCUPANCY 3:
// Wout streamed in two n-halves (34.8KB resident) -> smem 70.7KB/CTA.
// Warp = m16 x n32 per half; acc 16 regs. Half-1 W load overlaps half-0
// epilogue. Per-element accumulation order unchanged (bit-identical).
// smem: A region (34816: gather image then A tiles) | W half hi/lo (34816) | params
// ===========================================================================
#define O_A    0
#define O_W    34816
#define O_WLO  (O_W + 17408)
#define O_G    69632
#define O_B2   70144
#define O_SMEM 70656

__global__ __launch_bounds__(256, 3) void out_kernel(
    const float* __restrict__ gout, const float* __restrict__ bout,
    float* __restrict__ outp)
{
    extern __shared__ char sm[];
    const unsigned SB = smem_u32(sm);
    const int tid = threadIdx.x, lane = tid & 31, w = tid >> 5;
    const int g = lane >> 2, t2 = (lane & 3) * 2;
    const int wm = w >> 1, wn = w & 1;      // wm 0..3 (m16), wn 0..1 (n32 within half)
    const int m0 = wm * 16;
    const size_t base = (size_t)blockIdx.x * 64;

    // group 0: gather s tile [dd][64 fp32] into A region, rows 272B apart
    {
        const float* gs = g_s + base;
#pragma unroll
        for (int p = 0; p < 8; ++p) {
            int f = tid + p * 256;        // 0..2047
            int dd = f >> 4, u = f & 15;
            cp16(SB + O_A + dd * 272 + u * 16, gs + (size_t)dd * NN + u * 4);
        }
        CP_COMMIT();
    }
    // group 1: Wout n-half 0 (hi rows 0..63, lo rows 0..63)
    {
        const char* wh = g_wsp + 5 * (size_t)WMAT;
        const char* wl = wh + WPLANE;
#pragma unroll
        for (int q = 0; q < 9; ++q) {
            int t = tid + q * 256;
            if (t < 2176) {
                const char* src = (t < 1088) ? wh + (size_t)t * 16
                                             : wl + (size_t)(t - 1088) * 16;
                cp16(SB + O_W + t * 16, src);
            }
        }
        CP_COMMIT();
    }

    if (tid < 128) {
        ((float*)(sm + O_G))[tid]  = gout[tid];
        ((float*)(sm + O_B2))[tid] = bout[tid];
    }

    CP_WAIT1();            // gather done (W half 0 may still be in flight)
    __syncthreads();

    // LN over channels, reading Sf2[dd][row] (stride 68 floats), values buffered
    {
        const int row = tid >> 2, q = tid & 3;
        const float* Sf2 = (const float*)(sm + O_A);
        float sv[32];
        float s = 0.f, s2 = 0.f;
#pragma unroll
        for (int c = 0; c < 32; ++c) {
            float x = Sf2[(q * 32 + c) * 68 + row];
            sv[c] = x; s += x; s2 += x * x;
        }
        s  += __shfl_xor_sync(0xffffffffu, s, 1);  s2 += __shfl_xor_sync(0xffffffffu, s2, 1);
        s  += __shfl_xor_sync(0xffffffffu, s, 2);  s2 += __shfl_xor_sync(0xffffffffu, s2, 2);
        float mu = s * (1.f / 128.f);
        float rs = rsqrtf(fmaf(-mu, mu, s2 * (1.f / 128.f)) + 1e-5f);
        __syncthreads();   // all Sf2 reads complete before overwrite
        const float* G  = (const float*)(sm + O_G);
        const float* Bv = (const float*)(sm + O_B2);
#pragma unroll
        for (int c2 = 0; c2 < 16; ++c2) {
            int c = q * 32 + c2 * 2;
            float x0 = (sv[c2 * 2]     - mu) * rs * G[c]     + Bv[c];
            float x1 = (sv[c2 * 2 + 1] - mu) * rs * G[c + 1] + Bv[c + 1];
            unsigned hi, lo; split2(x0, x1, hi, lo);
            *(unsigned*)(sm + O_A       + (row * STR + c) * 2) = hi;
            *(unsigned*)(sm + O_A + APL + (row * STR + c) * 2) = lo;
        }
    }

    for (int half = 0; half < 2; ++half) {
        CP_WAIT0();            // W half resident
        __syncthreads();       // + A tiles visible (first iteration)

        float acc[4][4];
#pragma unroll
        for (int i = 0; i < 4; ++i)
#pragma unroll
            for (int j = 0; j < 4; ++j) acc[i][j] = 0.f;

#pragma unroll
        for (int ks = 0; ks < 8; ++ks) {
            const int k0 = ks * 16;
            unsigned ah[4], al[4];
            ldsm4(ah, ldsm_addr(SB + O_A,       lane, m0, k0, STR));
            ldsm4(al, ldsm_addr(SB + O_A + APL, lane, m0, k0, STR));
#pragma unroll
            for (int nb = 0; nb < 2; ++nb) {
                const int n0r = wn * 32 + nb * 16;   // row within half-tile
                unsigned bh[4], bl[4];
                ldsm4(bh, ldsm_addr(SB + O_W,   lane, n0r, k0, STR));
                ldsm4(bl, ldsm_addr(SB + O_WLO, lane, n0r, k0, STR));
                mma_bf16(acc[nb * 2],     ah, bh[0], bh[2]);
                mma_bf16(acc[nb * 2],     ah, bl[0], bl[2]);
                mma_bf16(acc[nb * 2],     al, bh[0], bh[2]);
                mma_bf16(acc[nb * 2 + 1], ah, bh[1], bh[3]);
                mma_bf16(acc[nb * 2 + 1], ah, bl[1], bl[3]);
                mma_bf16(acc[nb * 2 + 1], al, bh[1], bh[3]);
            }
        }
        __syncthreads();       // all warps done reading W half

        if (half == 0) {       // issue W half 1 — overlaps the epilogue below
            const char* wh = g_wsp + 5 * (size_t)WMAT + (size_t)64 * 272;
            const char* wl = wh + WPLANE;
#pragma unroll
            for (int q = 0; q < 9; ++q) {
                int t = tid + q * 256;
                if (t < 2176) {
                    const char* src = (t < 1088) ? wh + (size_t)t * 16
                                                 : wl + (size_t)(t - 1088) * 16;
                    cp16(SB + O_W + t * 16, src);
                }
            }
            CP_COMMIT();
        }

        // epilogue for this half's columns
        const size_t ijA = base + m0 + g, ijB = ijA + 8;
#pragma unroll
        for (int nt = 0; nt < 4; ++nt) {
            const int c0 = half * 64 + wn * 32 + nt * 8 + t2;
            float2 g0 = *(const float2*)&g_gate[ijA * 128 + c0];
            float2 g1 = *(const float2*)&g_gate[ijB * 128 + c0];
            *(float2*)&outp[ijA * 128 + c0] = make_float2(acc[nt][0] * g0.x, acc[nt][1] * g0.y);
            *(float2*)&outp[ijB * 128 + c0] = make_float2(acc[nt][2] * g1.x, acc[nt][3] * g1.y);
        }
    }
}

// ---------------------------------------------------------------------------
extern "C" void kernel_launch(void* const* d_in, const int* in_sizes, int n_in,
                              void* d_out, int out_size)
{
    const float* z    = (const float*)d_in[0];
    const float* gin  = (const float*)d_in[1];
    const float* bin  = (const float*)d_in[2];
    const float* gout = (const float*)d_in[3];
    const float* bout = (const float*)d_in[4];
    const float* Wa1  = (const float*)d_in[5];
    const float* Wa2  = (const float*)d_in[6];
    const float* Wb1  = (const float*)d_in[7];
    const float* Wb2  = (const float*)d_in[8];
    const float* Wg   = (const float*)d_in[9];
    const float* Wout = (const float*)d_in[10];
    float* out = (float*)d_out;

    cudaFuncSetAttribute(proj_kernel,   cudaFuncAttributeMaxDynamicSharedMemorySize, P_SMEM);
    cudaFuncSetAttribute(einsum_kernel, cudaFuncAttributeMaxDynamicSharedMemorySize, E_SMEM);
    cudaFuncSetAttribute(out_kernel,    cudaFuncAttributeMaxDynamicSharedMemorySize, O_SMEM);

    split_weights_kernel<<<192, 256>>>(Wa1, Wa2, Wb1, Wb2, Wg, Wout);
    proj_kernel<<<NN / 64, 256, P_SMEM>>>(z, gin, bin);
    einsum_kernel<<<dim3(Nn / 128, Nn / 128, Cc), 512, E_SMEM>>>();
    out_kernel<<<NN / 64, 256, O_SMEM>>>(gout, bout, out);
}

// round 17
// speedup vs baseline: 1.0689x; 1.0189x over previous
#include <cuda_runtime.h>
#include <cuda_bf16.h>
#include <math.h>

#define Nn 384
#define Cc 128
#define NN (Nn*Nn)   // 147456

// ---------------- global scratch (no allocations allowed) ------------------
__device__ __nv_bfloat16 g_ah[(size_t)Cc*NN];
__device__ __nv_bfloat16 g_al[(size_t)Cc*NN];
__device__ __nv_bfloat16 g_bh[(size_t)Cc*NN];
__device__ __nv_bfloat16 g_bl[(size_t)Cc*NN];
__device__ float g_gate[(size_t)Cc*NN];
__device__ float g_s[(size_t)Cc*NN];

// Pre-split weights as smem tile image: per matrix hi plane [128 x 272B], then lo.
#define WPLANE 34816
#define WMAT   (2*WPLANE)
__device__ __align__(16) char g_wsp[6*WMAT];

// ---------------- helpers ---------------------------------------------------
__device__ __forceinline__ unsigned smem_u32(const void* p) {
    unsigned a;
    asm("{ .reg .u64 t; cvta.to.shared.u64 t, %1; cvt.u32.u64 %0, t; }" : "=r"(a) : "l"(p));
    return a;
}
__device__ __forceinline__ void ldsm4(unsigned r[4], unsigned addr) {
    asm volatile("ldmatrix.sync.aligned.m8n8.x4.shared.b16 {%0,%1,%2,%3}, [%4];"
        : "=r"(r[0]), "=r"(r[1]), "=r"(r[2]), "=r"(r[3]) : "r"(addr));
}
__device__ __forceinline__ void mma_bf16(float c[4], const unsigned a[4], unsigned b0, unsigned b1) {
    asm volatile("mma.sync.aligned.m16n8k16.row.col.f32.bf16.bf16.f32 "
        "{%0,%1,%2,%3}, {%4,%5,%6,%7}, {%8,%9}, {%0,%1,%2,%3};"
        : "+f"(c[0]), "+f"(c[1]), "+f"(c[2]), "+f"(c[3])
        : "r"(a[0]), "r"(a[1]), "r"(a[2]), "r"(a[3]), "r"(b0), "r"(b1));
}
__device__ __forceinline__ unsigned ldsm_addr(unsigned base, int lane, int r0, int c0, int S) {
    int row = r0 + (lane & 7) + ((lane >> 3) & 1) * 8;
    int col = c0 + ((lane >> 4) << 3);
    return base + (unsigned)((row * S + col) * 2);
}
__device__ __forceinline__ void cp16(unsigned dst, const void* src) {
    asm volatile("cp.async.cg.shared.global [%0], [%1], 16;" :: "r"(dst), "l"(src));
}
#define CP_COMMIT() asm volatile("cp.async.commit_group;" ::: "memory")
#define CP_WAIT0()  asm volatile("cp.async.wait_group 0;" ::: "memory")
#define CP_WAIT1()  asm volatile("cp.async.wait_group 1;" ::: "memory")

__device__ __forceinline__ float sigm(float x) { return 1.f / (1.f + __expf(-x)); }

__device__ __forceinline__ void split2(float a, float b, unsigned& hi, unsigned& lo) {
    __nv_bfloat16 ha = __float2bfloat16(a), hb = __float2bfloat16(b);
    float ra = a - __bfloat162float(ha), rb = b - __bfloat162float(hb);
    __nv_bfloat16 la = __float2bfloat16(ra), lb = __float2bfloat16(rb);
    hi = (unsigned)__bfloat16_as_ushort(ha) | ((unsigned)__bfloat16_as_ushort(hb) << 16);
    lo = (unsigned)__bfloat16_as_ushort(la) | ((unsigned)__bfloat16_as_ushort(lb) << 16);
}

#define STR 136      // bf16 row stride for 128-col tiles (272B)
#define APL 17408    // 64-row A plane (64*272)

// ===========================================================================
// Kernel 0: split 6 weight matrices into smem-image layout
// ===========================================================================
__global__ __launch_bounds__(256) void split_weights_kernel(
    const float* __restrict__ Wa1, const float* __restrict__ Wa2,
    const float* __restrict__ Wb1, const float* __restrict__ Wb2,
    const float* __restrict__ Wg,  const float* __restrict__ Wout)
{
    int f = blockIdx.x * 256 + threadIdx.x;       // 6*128*64 = 49152
    int m = f >> 13;
    int rem = f & 8191;
    int h = rem >> 6, c2 = rem & 63;
    const float* W = (m == 0) ? Wa1 : (m == 1) ? Wa2 : (m == 2) ? Wb1 :
                     (m == 3) ? Wb2 : (m == 4) ? Wg : Wout;
    float x0 = W[h * 128 + c2 * 2], x1 = W[h * 128 + c2 * 2 + 1];
    unsigned hi, lo; split2(x0, x1, hi, lo);
    char* basep = g_wsp + (size_t)m * WMAT;
    *(unsigned*)(basep + h * 272 + c2 * 4)          = hi;
    *(unsigned*)(basep + WPLANE + h * 272 + c2 * 4) = lo;
}

// ===========================================================================
// Kernel 1: LN(z) + 5 projections. 64-row tiles, 256 thr, occupancy 2.
// (exact R12/R14 version)
// ===========================================================================
#define P_A   0
#define P_B   34816
#define P_GIN 104448
#define P_BIN 104960
#define P_SMEM 105472

__global__ __launch_bounds__(256, 2) void proj_kernel(
    const float* __restrict__ z,
    const float* __restrict__ gin, const float* __restrict__ bin)
{
    extern __shared__ char sm[];
    const unsigned SB = smem_u32(sm);
    const int tid = threadIdx.x, lane = tid & 31, w = tid >> 5;
    const int g = lane >> 2, t2 = (lane & 3) * 2;
    const int wm = w >> 1, wn = w & 1;
    const int m0 = wm * 16;
    const size_t base = (size_t)blockIdx.x * 64;

    // prefetch W0 into B region immediately (overlaps z load + LN)
    {
#pragma unroll
        for (int q = 0; q < 17; ++q) {
            int t = tid + q * 256;
            cp16(SB + P_B + t * 16, g_wsp + (size_t)t * 16);
        }
        CP_COMMIT();
    }

    if (tid < 128) {
        ((float*)(sm + P_GIN))[tid] = gin[tid];
        ((float*)(sm + P_BIN))[tid] = bin[tid];
    }

    // direct z load: row = tid>>2, cols q*32..q*32+31 (contiguous 128B/thread)
    {
        const int row = tid >> 2, q = tid & 3;
        float zv[32];
        const float4* zp = (const float4*)(z + (base + row) * 128 + q * 32);
#pragma unroll
        for (int i = 0; i < 8; ++i) {
            float4 v = zp[i];
            zv[i * 4]     = v.x; zv[i * 4 + 1] = v.y;
            zv[i * 4 + 2] = v.z; zv[i * 4 + 3] = v.w;
        }
        float s = 0.f, s2 = 0.f;
#pragma unroll
        for (int i = 0; i < 32; ++i) { s += zv[i]; s2 += zv[i] * zv[i]; }
        s  += __shfl_xor_sync(0xffffffffu, s, 1);  s2 += __shfl_xor_sync(0xffffffffu, s2, 1);
        s  += __shfl_xor_sync(0xffffffffu, s, 2);  s2 += __shfl_xor_sync(0xffffffffu, s2, 2);
        float mu = s * (1.f / 128.f);
        float rs = rsqrtf(fmaf(-mu, mu, s2 * (1.f / 128.f)) + 1e-5f);
        __syncthreads();          // params visible
        const float* G  = (const float*)(sm + P_GIN);
        const float* Bv = (const float*)(sm + P_BIN);
#pragma unroll
        for (int c2 = 0; c2 < 16; ++c2) {
            int c = q * 32 + c2 * 2;
            float x0 = (zv[c2 * 2]     - mu) * rs * G[c]     + Bv[c];
            float x1 = (zv[c2 * 2 + 1] - mu) * rs * G[c + 1] + Bv[c + 1];
            unsigned hi, lo; split2(x0, x1, hi, lo);
            *(unsigned*)(sm + P_A       + (row * STR + c) * 2) = hi;
            *(unsigned*)(sm + P_A + APL + (row * STR + c) * 2) = lo;
        }
    }

    float keep[8][4];

    for (int m = 0; m < 5; ++m) {
        if (m > 0) {      // W0 already issued at entry
            const char* srcb = g_wsp + (size_t)m * WMAT;
#pragma unroll
            for (int q = 0; q < 17; ++q) {
                int t = tid + q * 256;
                cp16(SB + P_B + t * 16, srcb + (size_t)t * 16);
            }
            CP_COMMIT();
        }
        CP_WAIT0();
        __syncthreads();          // W[m] + A tiles visible to all

        float acc[8][4];
#pragma unroll
        for (int i = 0; i < 8; ++i)
#pragma unroll
            for (int j = 0; j < 4; ++j) acc[i][j] = 0.f;

#pragma unroll
        for (int ks = 0; ks < 8; ++ks) {
            const int k0 = ks * 16;
            unsigned ah[4], al[4];
            ldsm4(ah, ldsm_addr(SB + P_A,       lane, m0, k0, STR));
            ldsm4(al, ldsm_addr(SB + P_A + APL, lane, m0, k0, STR));
#pragma unroll
            for (int nb = 0; nb < 4; ++nb) {
                const int n0 = wn * 64 + nb * 16;
                unsigned bh[4], bl[4];
                ldsm4(bh, ldsm_addr(SB + P_B,          lane, n0, k0, STR));
                ldsm4(bl, ldsm_addr(SB + P_B + WPLANE, lane, n0, k0, STR));
                mma_bf16(acc[nb * 2],     ah, bh[0], bh[2]);
                mma_bf16(acc[nb * 2],     ah, bl[0], bl[2]);
                mma_bf16(acc[nb * 2],     al, bh[0], bh[2]);
                mma_bf16(acc[nb * 2 + 1], ah, bh[1], bh[3]);
                mma_bf16(acc[nb * 2 + 1], ah, bl[1], bl[3]);
                mma_bf16(acc[nb * 2 + 1], al, bh[1], bh[3]);
            }
        }
        __syncthreads();   // all warps done reading B

        if (m == 0 || m == 2) {
#pragma unroll
            for (int i = 0; i < 8; ++i)
#pragma unroll
                for (int j = 0; j < 4; ++j) keep[i][j] = sigm(acc[i][j]);
        } else if (m == 1 || m == 3) {
            // transpose through smem stage in B region: [d][ij], 144B rows
            __nv_bfloat16* stH = (__nv_bfloat16*)(sm + P_B);
            __nv_bfloat16* stL = (__nv_bfloat16*)(sm + P_B + 18432);
            const int ijA = m0 + g, ijB = ijA + 8;
#pragma unroll
            for (int nt = 0; nt < 8; ++nt) {
                const int d0 = wn * 64 + nt * 8 + t2;
                float v00 = keep[nt][0] * acc[nt][0];
                float v01 = keep[nt][1] * acc[nt][1];
                float v10 = keep[nt][2] * acc[nt][2];
                float v11 = keep[nt][3] * acc[nt][3];
                __nv_bfloat16 h;
                h = __float2bfloat16(v00); stH[d0 * 72 + ijA] = h;
                stL[d0 * 72 + ijA] = __float2bfloat16(v00 - __bfloat162float(h));
                h = __float2bfloat16(v01); stH[(d0 + 1) * 72 + ijA] = h;
                stL[(d0 + 1) * 72 + ijA] = __float2bfloat16(v01 - __bfloat162float(h));
                h = __float2bfloat16(v10); stH[d0 * 72 + ijB] = h;
                stL[d0 * 72 + ijB] = __float2bfloat16(v10 - __bfloat162float(h));
                h = __float2bfloat16(v11); stH[(d0 + 1) * 72 + ijB] = h;
                stL[(d0 + 1) * 72 + ijB] = __float2bfloat16(v11 - __bfloat162float(h));
            }
            __syncthreads();
            __nv_bfloat16* ph = (m == 1) ? g_ah : g_bh;
            __nv_bfloat16* pl = (m == 1) ? g_al : g_bl;
#pragma unroll
            for (int p = 0; p < 8; ++p) {
                int f = tid + p * 256;          // 0..2047
                int plane = f >> 10, rem = f & 1023;
                int d = rem >> 3, u = rem & 7;
                uint4 v = *(const uint4*)(sm + P_B + plane * 18432 + d * 144 + u * 16);
                __nv_bfloat16* gp = plane ? pl : ph;
                *(uint4*)(gp + (size_t)d * NN + base + u * 8) = v;
            }
        } else {
            const size_t ijA = base + m0 + g, ijB = ijA + 8;
#pragma unroll
            for (int nt = 0; nt < 8; ++nt) {
                const int c0 = wn * 64 + nt * 8 + t2;
                *(float2*)&g_gate[ijA * 128 + c0] = make_float2(sigm(acc[nt][0]), sigm(acc[nt][1]));
                *(float2*)&g_gate[ijB * 128 + c0] = make_float2(sigm(acc[nt][2]), sigm(acc[nt][3]));
            }
        }
        __syncthreads();   // B region free for next matrix
    }
}

// ===========================================================================
// Kernel 2: einsum, 128x128 tile, 512 thr (16 warps 2x8, warp = m64 x n16),
// K chunks of 32, 3-slot cp.async ring (3x32KB = 96KB), ONE sync per chunk:
// after wait+sync all warps are past iter c-1, so staging slot (c+2)%3
// (== (c-1)%3) is race-free and overlaps this iteration's MMA.
// occupancy 2 (2x96KB = 192KB <= 228KB/SM).
// ===========================================================================
#define E_BUF 32768
#define E_SMEM (3*E_BUF)

__global__ __launch_bounds__(512, 2) void einsum_kernel()
{
    extern __shared__ char sm[];
    const unsigned SB = smem_u32(sm);
    const int tid = threadIdx.x, lane = tid & 31, w = tid >> 5;
    const int g = lane >> 2, t2 = (lane & 3) * 2;
    const int wr = w >> 3, wc = w & 7;          // 2 x 8 warp grid
    const int m0w = wr * 64, n0w = wc * 16;
    const int d = blockIdx.z, i0 = blockIdx.y * 128, j0 = blockIdx.x * 128;

    const __nv_bfloat16* pah = g_ah + (size_t)d * NN + (size_t)i0 * Nn;
    const __nv_bfloat16* pal = g_al + (size_t)d * NN + (size_t)i0 * Nn;
    const __nv_bfloat16* pbh = g_bh + (size_t)d * NN + (size_t)j0 * Nn;
    const __nv_bfloat16* pbl = g_bl + (size_t)d * NN + (size_t)j0 * Nn;

    auto eaddr = [&](unsigned pbase, int r0, int kk) -> unsigned {
        int row = r0 + (lane & 7) + ((lane >> 3) & 1) * 8;
        int ch = (kk >> 3) + ((lane >> 4) & 1);
        ch ^= (row >> 1) & 3;
        return pbase + (unsigned)(row * 64 + ch * 16);
    };

    auto stage = [&](int c, int b) {
        const int k0 = c * 32;
        const unsigned dstb = SB + b * E_BUF;
#pragma unroll
        for (int q = 0; q < 4; ++q) {
            int u = q * 512 + tid;            // 0..2047
            int p = u >> 9, rem = u & 511;
            int r = rem >> 2, sg = rem & 3;
            int sw = sg ^ ((r >> 1) & 3);
            const __nv_bfloat16* src = (p == 0) ? pah : (p == 1) ? pal : (p == 2) ? pbh : pbl;
            cp16(dstb + p * 8192 + r * 64 + sw * 16,
                 src + (size_t)r * Nn + k0 + sg * 8);
        }
        CP_COMMIT();
    };

    float acc[8][4];
#pragma unroll
    for (int i = 0; i < 8; ++i)
#pragma unroll
        for (int j = 0; j < 4; ++j) acc[i][j] = 0.f;

    stage(0, 0);
    stage(1, 1);

    for (int c = 0; c < 12; ++c) {
        if (c < 11) { CP_WAIT1(); } else { CP_WAIT0(); }
        __syncthreads();                     // all warps past iter c-1
        if (c + 2 < 12) stage(c + 2, (c + 2) % 3);   // slot (c-1)%3: free

        const unsigned B = SB + (c % 3) * E_BUF;
#pragma unroll
        for (int ks = 0; ks < 2; ++ks) {
            const int kk = ks * 16;
            unsigned tb[4];
            ldsm4(tb, eaddr(B + 16384, n0w, kk));
            unsigned bhA0 = tb[0], bhA1 = tb[2], bhB0 = tb[1], bhB1 = tb[3];
            ldsm4(tb, eaddr(B + 24576, n0w, kk));
            unsigned blA0 = tb[0], blA1 = tb[2], blB0 = tb[1], blB1 = tb[3];
#pragma unroll
            for (int mt = 0; mt < 4; ++mt) {
                unsigned ah[4], al[4];
                ldsm4(ah, eaddr(B,        m0w + mt * 16, kk));
                ldsm4(al, eaddr(B + 8192, m0w + mt * 16, kk));
                mma_bf16(acc[mt * 2],     ah, bhA0, bhA1);
                mma_bf16(acc[mt * 2],     ah, blA0, blA1);
                mma_bf16(acc[mt * 2],     al, bhA0, bhA1);
                mma_bf16(acc[mt * 2 + 1], ah, bhB0, bhB1);
                mma_bf16(acc[mt * 2 + 1], ah, blB0, blB1);
                mma_bf16(acc[mt * 2 + 1], al, bhB0, bhB1);
            }
        }
    }

    float* plane = g_s + (size_t)d * NN;
#pragma unroll
    for (int mt = 0; mt < 4; ++mt)
#pragma unroll
        for (int nf = 0; nf < 2; ++nf) {
            int row = m0w + mt * 16 + g;
            int col = n0w + nf * 8 + t2;
            float* pr = plane + (size_t)(i0 + row) * Nn + (j0 + col);
            *(float2*)pr            = make_float2(acc[mt * 2 + nf][0], acc[mt * 2 + nf][1]);
            *(float2*)(pr + 8 * Nn) = make_float2(acc[mt * 2 + nf][2], acc[mt * 2 + nf][3]);
        }
}

// ===========================================================================
// Kernel 3: LN(s over d) + Wout + gate. 64-row tiles, 256 thr, occupancy 3.
// (exact R15 version)
// ===========================================================================
#define O_A    0
#define O_W    34816
#define O_WLO  (O_W + 17408)
#define O_G    69632
#define O_B2   70144
#define O_SMEM 70656

__global__ __launch_bounds__(256, 3) void out_kernel(
    const float* __restrict__ gout, const float* __restrict__ bout,
    float* __restrict__ outp)
{
    extern __shared__ char sm[];
    const unsigned SB = smem_u32(sm);
    const int tid = threadIdx.x, lane = tid & 31, w = tid >> 5;
    const int g = lane >> 2, t2 = (lane & 3) * 2;
    const int wm = w >> 1, wn = w & 1;      // wm 0..3 (m16), wn 0..1 (n32 within half)
    const int m0 = wm * 16;
    const size_t base = (size_t)blockIdx.x * 64;

    // group 0: gather s tile [dd][64 fp32] into A region, rows 272B apart
    {
        const float* gs = g_s + base;
#pragma unroll
        for (int p = 0; p < 8; ++p) {
            int f = tid + p * 256;        // 0..2047
            int dd = f >> 4, u = f & 15;
            cp16(SB + O_A + dd * 272 + u * 16, gs + (size_t)dd * NN + u * 4);
        }
        CP_COMMIT();
    }
    // group 1: Wout n-half 0 (hi rows 0..63, lo rows 0..63)
    {
        const char* wh = g_wsp + 5 * (size_t)WMAT;
        const char* wl = wh + WPLANE;
#pragma unroll
        for (int q = 0; q < 9; ++q) {
            int t = tid + q * 256;
            if (t < 2176) {
                const char* src = (t < 1088) ? wh + (size_t)t * 16
                                             : wl + (size_t)(t - 1088) * 16;
                cp16(SB + O_W + t * 16, src);
            }
        }
        CP_COMMIT();
    }

    if (tid < 128) {
        ((float*)(sm + O_G))[tid]  = gout[tid];
        ((float*)(sm + O_B2))[tid] = bout[tid];
    }

    CP_WAIT1();            // gather done (W half 0 may still be in flight)
    __syncthreads();

    // LN over channels, reading Sf2[dd][row] (stride 68 floats), values buffered
    {
        const int row = tid >> 2, q = tid & 3;
        const float* Sf2 = (const float*)(sm + O_A);
        float sv[32];
        float s = 0.f, s2 = 0.f;
#pragma unroll
        for (int c = 0; c < 32; ++c) {
            float x = Sf2[(q * 32 + c) * 68 + row];
            sv[c] = x; s += x; s2 += x * x;
        }
        s  += __shfl_xor_sync(0xffffffffu, s, 1);  s2 += __shfl_xor_sync(0xffffffffu, s2, 1);
        s  += __shfl_xor_sync(0xffffffffu, s, 2);  s2 += __shfl_xor_sync(0xffffffffu, s2, 2);
        float mu = s * (1.f / 128.f);
        float rs = rsqrtf(fmaf(-mu, mu, s2 * (1.f / 128.f)) + 1e-5f);
        __syncthreads();   // all Sf2 reads complete before overwrite
        const float* G  = (const float*)(sm + O_G);
        const float* Bv = (const float*)(sm + O_B2);
#pragma unroll
        for (int c2 = 0; c2 < 16; ++c2) {
            int c = q * 32 + c2 * 2;
            float x0 = (sv[c2 * 2]     - mu) * rs * G[c]     + Bv[c];
            float x1 = (sv[c2 * 2 + 1] - mu) * rs * G[c + 1] + Bv[c + 1];
            unsigned hi, lo; split2(x0, x1, hi, lo);
            *(unsigned*)(sm + O_A       + (row * STR + c) * 2) = hi;
            *(unsigned*)(sm + O_A + APL + (row * STR + c) * 2) = lo;
        }
    }

    for (int half = 0; half < 2; ++half) {
        CP_WAIT0();            // W half resident
        __syncthreads();       // + A tiles visible (first iteration)

        float acc[4][4];
#pragma unroll
        for (int i = 0; i < 4; ++i)
#pragma unroll
            for (int j = 0; j < 4; ++j) acc[i][j] = 0.f;

#pragma unroll
        for (int ks = 0; ks < 8; ++ks) {
            const int k0 = ks * 16;
            unsigned ah[4], al[4];
            ldsm4(ah, ldsm_addr(SB + O_A,       lane, m0, k0, STR));
            ldsm4(al, ldsm_addr(SB + O_A + APL, lane, m0, k0, STR));
#pragma unroll
            for (int nb = 0; nb < 2; ++nb) {
                const int n0r = wn * 32 + nb * 16;   // row within half-tile
                unsigned bh[4], bl[4];
                ldsm4(bh, ldsm_addr(SB + O_W,   lane, n0r, k0, STR));
                ldsm4(bl, ldsm_addr(SB + O_WLO, lane, n0r, k0, STR));
                mma_bf16(acc[nb * 2],     ah, bh[0], bh[2]);
                mma_bf16(acc[nb * 2],     ah, bl[0], bl[2]);
                mma_bf16(acc[nb * 2],     al, bh[0], bh[2]);
                mma_bf16(acc[nb * 2 + 1], ah, bh[1], bh[3]);
                mma_bf16(acc[nb * 2 + 1], ah, bl[1], bl[3]);
                mma_bf16(acc[nb * 2 + 1], al, bh[1], bh[3]);
            }
        }
        __syncthreads();       // all warps done reading W half

        if (half == 0) {       // issue W half 1 — overlaps the epilogue below
            const char* wh = g_wsp + 5 * (size_t)WMAT + (size_t)64 * 272;
            const char* wl = wh + WPLANE;
#pragma unroll
            for (int q = 0; q < 9; ++q) {
                int t = tid + q * 256;
                if (t < 2176) {
                    const char* src = (t < 1088) ? wh + (size_t)t * 16
                                                 : wl + (size_t)(t - 1088) * 16;
                    cp16(SB + O_W + t * 16, src);
                }
            }
            CP_COMMIT();
        }

        // epilogue for this half's columns
        const size_t ijA = base + m0 + g, ijB = ijA + 8;
#pragma unroll
        for (int nt = 0; nt < 4; ++nt) {
            const int c0 = half * 64 + wn * 32 + nt * 8 + t2;
            float2 g0 = *(const float2*)&g_gate[ijA * 128 + c0];
            float2 g1 = *(const float2*)&g_gate[ijB * 128 + c0];
            *(float2*)&outp[ijA * 128 + c0] = make_float2(acc[nt][0] * g0.x, acc[nt][1] * g0.y);
            *(float2*)&outp[ijB * 128 + c0] = make_float2(acc[nt][2] * g1.x, acc[nt][3] * g1.y);
        }
    }
}

// ---------------------------------------------------------------------------
extern "C" void kernel_launch(void* const* d_in, const int* in_sizes, int n_in,
                              void* d_out, int out_size)
{
    const float* z    = (const float*)d_in[0];
    const float* gin  = (const float*)d_in[1];
    const float* bin  = (const float*)d_in[2];
    const float* gout = (const float*)d_in[3];
    const float* bout = (const float*)d_in[4];
    const float* Wa1  = (const float*)d_in[5];
    const float* Wa2  = (const float*)d_in[6];
    const float* Wb1  = (const float*)d_in[7];
    const float* Wb2  = (const float*)d_in[8];
    const float* Wg   = (const float*)d_in[9];
    const float* Wout = (const float*)d_in[10];
    float* out = (float*)d_out;

    cudaFuncSetAttribute(proj_kernel,   cudaFuncAttributeMaxDynamicSharedMemorySize, P_SMEM);
    cudaFuncSetAttribute(einsum_kernel, cudaFuncAttributeMaxDynamicSharedMemorySize, E_SMEM);
    cudaFuncSetAttribute(out_kernel,    cudaFuncAttributeMaxDynamicSharedMemorySize, O_SMEM);

    split_weights_kernel<<<192, 256>>>(Wa1, Wa2, Wb1, Wb2, Wg, Wout);
    proj_kernel<<<NN / 64, 256, P_SMEM>>>(z, gin, bin);
    einsum_kernel<<<dim3(Nn / 128, Nn / 128, Cc), 512, E_SMEM>>>();
    out_kernel<<<NN / 64, 256, O_SMEM>>>(gout, bout, out);
}